// round 6
// baseline (speedup 1.0000x reference)
#include <cuda_runtime.h>
#include <math.h>
#include <stdint.h>

#define NT 1024
#define NV 128
#define NXS 512
#define NVX 65536          // NV*NXS (contraction length of GEMM1)
#define KDIM 257
#define KP 288             // padded KDIM (2 x 144)
#define NXOUT 2048

// -------- scratch (no allocations allowed) --------
__device__ float g_psiT[(size_t)KP * NVX];    // transposed psi * (hx*hv), tf32-rounded
__device__ float g_w[(size_t)NT * KP];        // weights accumulator
__device__ float g_phi[(size_t)KP * NXOUT];   // fourier basis (rows >= 257 zero)

// ============================ helpers ============================
__device__ __forceinline__ uint32_t smem_u32(const void* p) {
    uint32_t a;
    asm("{ .reg .u64 t; cvta.to.shared.u64 t, %1; cvt.u32.u64 %0, t; }" : "=r"(a) : "l"(p));
    return a;
}
__device__ __forceinline__ uint32_t rna_tf32(float x) {
    uint32_t r;
    asm("cvt.rna.tf32.f32 %0, %1;" : "=r"(r) : "f"(x));
    return r;
}
__device__ __forceinline__ void mma_tf32(float* c, const uint32_t* a, uint32_t b0, uint32_t b1) {
    asm volatile(
        "mma.sync.aligned.m16n8k8.row.col.f32.tf32.tf32.f32 "
        "{%0,%1,%2,%3}, {%4,%5,%6,%7}, {%8,%9}, {%0,%1,%2,%3};"
        : "+f"(c[0]), "+f"(c[1]), "+f"(c[2]), "+f"(c[3])
        : "r"(a[0]), "r"(a[1]), "r"(a[2]), "r"(a[3]), "r"(b0), "r"(b1));
}
__device__ __forceinline__ void cp_async16(uint32_t dst, const void* src) {
    asm volatile("cp.async.ca.shared.global [%0], [%1], 16;" :: "r"(dst), "l"(src) : "memory");
}
__device__ __forceinline__ void cp_commit() { asm volatile("cp.async.commit_group;" ::: "memory"); }
__device__ __forceinline__ void cp_wait0()  { asm volatile("cp.async.wait_group 0;" ::: "memory"); }

// ---------------- Psi MLP: (x,v) -> 257, transposed + scaled + tf32-rounded ----------------
__global__ void psi_kernel(const float* __restrict__ xs, const float* __restrict__ vs,
                           const float* __restrict__ W1, const float* __restrict__ b1,
                           const float* __restrict__ W2, const float* __restrict__ b2,
                           const float* __restrict__ W3, const float* __restrict__ b3)
{
    __shared__ float sW1[128];
    __shared__ float sb1[64];
    __shared__ float sW2[64 * 32];
    __shared__ float sb2[32];
    __shared__ float sW3[32 * KDIM];
    __shared__ float sb3[KDIM];

    int tid = threadIdx.x;
    for (int i = tid; i < 128; i += 256)       sW1[i] = W1[i];
    for (int i = tid; i < 64; i += 256)        sb1[i] = b1[i];
    for (int i = tid; i < 64 * 32; i += 256)   sW2[i] = W2[i];
    if (tid < 32)                              sb2[tid] = b2[tid];
    for (int i = tid; i < 32 * KDIM; i += 256) sW3[i] = W3[i];
    for (int i = tid; i < KDIM; i += 256)      sb3[i] = b3[i];
    __syncthreads();

    int p = blockIdx.x * 256 + tid;
    int v = p >> 9;
    int x = p & 511;
    float xin = xs[x];
    float vin = vs[v];
    float scale = (xs[1] - xs[0]) * (vs[1] - vs[0]);   // hx * hv

    float h1[64];
#pragma unroll
    for (int j = 0; j < 64; j++) {
        float s = fmaf(xin, sW1[j], fmaf(vin, sW1[64 + j], sb1[j]));
        h1[j] = fmaxf(s, 0.0f);
    }
    float h2[32];
#pragma unroll
    for (int j = 0; j < 32; j++) {
        float s = sb2[j];
#pragma unroll
        for (int i = 0; i < 64; i++) s = fmaf(h1[i], sW2[i * 32 + j], s);
        h2[j] = fmaxf(s, 0.0f);
    }
    for (int k = 0; k < KDIM; k++) {
        float s = sb3[k];
#pragma unroll
        for (int j = 0; j < 32; j++) s = fmaf(h2[j], sW3[j * KDIM + k], s);
        g_psiT[(size_t)k * NVX + p] = __uint_as_float(rna_tf32(s * scale));
    }
}

// ---------------- zero g_w + padding rows of psiT/phi ----------------
#define ZERO_TOTAL (NT * KP + (KP - KDIM) * NVX + (KP - KDIM) * NXOUT)
__global__ void zero_misc_kernel()
{
    int i = blockIdx.x * 256 + threadIdx.x;
    if (i < NT * KP) { g_w[i] = 0.0f; return; }
    i -= NT * KP;
    if (i < (KP - KDIM) * NVX) { g_psiT[(size_t)KDIM * NVX + i] = 0.0f; return; }
    i -= (KP - KDIM) * NVX;
    if (i < (KP - KDIM) * NXOUT) g_phi[(size_t)KDIM * NXOUT + i] = 0.0f;
}

// ---------------- phi table: (K, Nx_out) ----------------
__global__ void phi_kernel(const float* __restrict__ x_out, const float* __restrict__ xs)
{
    int idx = blockIdx.x * 256 + threadIdx.x;
    if (idx >= KDIM * NXOUT) return;
    int r = idx / NXOUT;
    int x = idx - r * NXOUT;
    float w = (2.0f * 3.14159265358979323846f) / (xs[NXS - 1] - xs[0]);
    float xo = x_out[x];
    float val;
    if (r < 128) val = sinf((float)(r + 1) * w * xo);
    else         val = cosf((float)(r - 128) * w * xo);
    g_phi[idx] = val;
}

// ---------------- GEMM1 via mma.sync tf32 ----------------
// C (1024 x 288) += f (1024 x 65536) @ psiT^T
// CTA tile 256x144, BK=32, 512 threads: warps 8(M) x 2(N), warp tile 32x72, split-K 16.
// SA/SB = 36: bank = (4q+j)%32 -> conflict-free fragment access.
#define BM 256
#define BN 144
#define BK 32
#define SPLITS 16
#define KCHUNK (NVX / SPLITS)    // 4096
#define NIT (KCHUNK / BK)        // 128
#define SA 36
#define SB 36
#define A_FLOATS (BM * SA)       // 9216 per stage
#define B_FLOATS (BN * SB)       // 5184 per stage
#define SMEM_FLOATS (2 * A_FLOATS + 2 * B_FLOATS)   // 28800 floats = 115200 B
#define B_VEC (BN * 8)           // 1152 float4 loads per B tile

__global__ void __launch_bounds__(512, 1) gemm1_mma(const float* __restrict__ f)
{
    extern __shared__ __align__(16) float sm[];
    float* As[2] = { sm, sm + A_FLOATS };
    float* Bs[2] = { sm + 2 * A_FLOATS, sm + 2 * A_FLOATS + B_FLOATS };
    uint32_t sm_b = smem_u32(sm);
    uint32_t bs_u32[2] = { sm_b + 2 * A_FLOATS * 4, sm_b + (2 * A_FLOATS + B_FLOATS) * 4 };

    const int tid = threadIdx.x;
    const int lane = tid & 31;
    const int warp = tid >> 5;               // 0..15
    const int wm = warp & 7;                 // 0..7 (M)
    const int wn = warp >> 3;                // 0..1 (N)
    const int q = lane >> 2, j = lane & 3;

    const int row0 = blockIdx.y * BM;
    const int col0 = blockIdx.x * BN;
    const size_t kb0 = (size_t)blockIdx.z * KCHUNK;

    const int lrow = tid >> 3;               // 0..63
    const int loct = tid & 7;                // 0..7

    float acc[2][9][4];
#pragma unroll
    for (int a = 0; a < 2; a++)
#pragma unroll
        for (int b = 0; b < 9; b++)
#pragma unroll
            for (int c = 0; c < 4; c++) acc[a][b][c] = 0.0f;

    // ---- prologue: fill stage 0 ----
    {
#pragma unroll
        for (int p = 0; p < 3; p++) {
            int idx = tid + p * 512;
            if (idx < B_VEC) {
                int r = idx >> 3, o = idx & 7;
                cp_async16(bs_u32[0] + (uint32_t)(r * SB + o * 4) * 4,
                           g_psiT + (size_t)(col0 + r) * NVX + kb0 + o * 4);
            }
        }
        cp_commit();
#pragma unroll
        for (int i = 0; i < 4; i++) {
            int r = lrow + i * 64;
            float4 v = *(const float4*)(f + (size_t)(row0 + r) * NVX + kb0 + loct * 4);
            uint4 u;
            u.x = rna_tf32(v.x); u.y = rna_tf32(v.y); u.z = rna_tf32(v.z); u.w = rna_tf32(v.w);
            *(uint4*)(As[0] + r * SA + loct * 4) = u;
        }
        cp_wait0();
        __syncthreads();
    }

    float4 av[4];
    for (int it = 0; it < NIT; ++it) {
        const int s = it & 1;
        const bool pf = (it + 1 < NIT);
        const size_t kb = kb0 + (size_t)(it + 1) * BK;

        if (pf) {
#pragma unroll
            for (int p = 0; p < 3; p++) {
                int idx = tid + p * 512;
                if (idx < B_VEC) {
                    int r = idx >> 3, o = idx & 7;
                    cp_async16(bs_u32[s ^ 1] + (uint32_t)(r * SB + o * 4) * 4,
                               g_psiT + (size_t)(col0 + r) * NVX + kb + o * 4);
                }
            }
            cp_commit();
#pragma unroll
            for (int i = 0; i < 4; i++)
                av[i] = *(const float4*)(f + (size_t)(row0 + lrow + i * 64) * NVX + kb + loct * 4);
        }

        // ---- compute 4 k8-steps on stage s ----
        const float* Ab = As[s];
        const float* Bb = Bs[s];
#pragma unroll
        for (int kk = 0; kk < 4; kk++) {
            uint32_t afr[2][4];
#pragma unroll
            for (int mt = 0; mt < 2; mt++) {
                const float* ap = Ab + (wm * 32 + mt * 16 + q) * SA + kk * 8 + j;
                afr[mt][0] = __float_as_uint(ap[0]);
                afr[mt][1] = __float_as_uint(ap[8 * SA]);
                afr[mt][2] = __float_as_uint(ap[4]);
                afr[mt][3] = __float_as_uint(ap[8 * SA + 4]);
            }
#pragma unroll
            for (int nt = 0; nt < 9; nt++) {
                const float* bp = Bb + (wn * 72 + nt * 8 + q) * SB + kk * 8 + j;
                uint32_t b0 = __float_as_uint(bp[0]);
                uint32_t b1 = __float_as_uint(bp[4]);
#pragma unroll
                for (int mt = 0; mt < 2; mt++)
                    mma_tf32(acc[mt][nt], afr[mt], b0, b1);
            }
        }

        if (pf) {
#pragma unroll
            for (int i = 0; i < 4; i++) {
                uint4 u;
                u.x = rna_tf32(av[i].x); u.y = rna_tf32(av[i].y);
                u.z = rna_tf32(av[i].z); u.w = rna_tf32(av[i].w);
                *(uint4*)(As[s ^ 1] + (lrow + i * 64) * SA + loct * 4) = u;
            }
            cp_wait0();
        }
        __syncthreads();
    }

    // ---- epilogue: atomic accumulate into g_w ----
#pragma unroll
    for (int mt = 0; mt < 2; mt++) {
        int r0 = row0 + wm * 32 + mt * 16 + q;
#pragma unroll
        for (int nt = 0; nt < 9; nt++) {
            int c0 = col0 + wn * 72 + nt * 8 + 2 * j;
            atomicAdd(&g_w[(size_t)r0 * KP + c0],           acc[mt][nt][0]);
            atomicAdd(&g_w[(size_t)r0 * KP + c0 + 1],       acc[mt][nt][1]);
            atomicAdd(&g_w[(size_t)(r0 + 8) * KP + c0],     acc[mt][nt][2]);
            atomicAdd(&g_w[(size_t)(r0 + 8) * KP + c0 + 1], acc[mt][nt][3]);
        }
    }
}

// ---------------- GEMM2: out = g_w (NT x KP) @ g_phi (KP x NXOUT) ----------------
#define G2_BM 64
#define G2_BN 64
#define G2_BK 16

__global__ void gemm2_kernel(float* __restrict__ out)
{
    __shared__ __align__(16) float As2[G2_BK][G2_BM + 4];
    __shared__ __align__(16) float Bs2[G2_BK][G2_BN];

    int nt = blockIdx.x;
    int mt = blockIdx.y;
    int tid = threadIdx.x;
    int tx = tid & 15;
    int ty = tid >> 4;

    int row0 = mt * G2_BM;
    int col0 = nt * G2_BN;

    float acc[4][4];
#pragma unroll
    for (int r = 0; r < 4; r++)
#pragma unroll
        for (int c = 0; c < 4; c++) acc[r][c] = 0.0f;

    for (int kc = 0; kc < KP; kc += G2_BK) {
#pragma unroll
        for (int i = 0; i < 4; i++) {
            int l = tid + i * 256;
            int mrow = l >> 4;
            int kk = l & 15;
            As2[kk][mrow] = g_w[(size_t)(row0 + mrow) * KP + kc + kk];
        }
#pragma unroll
        for (int i = 0; i < 4; i++) {
            int l = tid + i * 256;
            int kk = l >> 6;
            int n = l & 63;
            Bs2[kk][n] = g_phi[(size_t)(kc + kk) * NXOUT + col0 + n];
        }
        __syncthreads();
#pragma unroll
        for (int kk = 0; kk < G2_BK; kk++) {
            float4 a = *(const float4*)&As2[kk][ty * 4];
            float4 b = *(const float4*)&Bs2[kk][tx * 4];
            float avv[4] = {a.x, a.y, a.z, a.w};
            float bvv[4] = {b.x, b.y, b.z, b.w};
#pragma unroll
            for (int r = 0; r < 4; r++)
#pragma unroll
                for (int c = 0; c < 4; c++)
                    acc[r][c] = fmaf(avv[r], bvv[c], acc[r][c]);
        }
        __syncthreads();
    }

#pragma unroll
    for (int r = 0; r < 4; r++) {
        int gm = row0 + ty * 4 + r;
#pragma unroll
        for (int c = 0; c < 4; c++) {
            int gn = col0 + tx * 4 + c;
            out[(size_t)gm * NXOUT + gn] = acc[r][c];
        }
    }
}

extern "C" void kernel_launch(void* const* d_in, const int* in_sizes, int n_in,
                              void* d_out, int out_size)
{
    const float* x_out = (const float*)d_in[0];
    const float* f     = (const float*)d_in[1];
    const float* xs    = (const float*)d_in[2];
    const float* vs    = (const float*)d_in[3];
    const float* W1    = (const float*)d_in[4];
    const float* b1    = (const float*)d_in[5];
    const float* W2    = (const float*)d_in[6];
    const float* b2    = (const float*)d_in[7];
    const float* W3    = (const float*)d_in[8];
    const float* b3    = (const float*)d_in[9];
    float* out = (float*)d_out;

    static int smem_set = 0;
    if (!smem_set) {
        cudaFuncSetAttribute(gemm1_mma, cudaFuncAttributeMaxDynamicSharedMemorySize,
                             SMEM_FLOATS * 4);
        smem_set = 1;
    }

    psi_kernel<<<NVX / 256, 256>>>(xs, vs, W1, b1, W2, b2, W3, b3);
    zero_misc_kernel<<<(ZERO_TOTAL + 255) / 256, 256>>>();
    phi_kernel<<<(KDIM * NXOUT + 255) / 256, 256>>>(x_out, xs);
    {
        dim3 grid(2, 4, SPLITS);   // N tiles, M tiles, split-K
        gemm1_mma<<<grid, 512, SMEM_FLOATS * 4>>>(f);
    }
    {
        dim3 grid(NXOUT / G2_BN, NT / G2_BM);
        gemm2_kernel<<<grid, 256>>>(out);
    }
}

// round 7
// speedup vs baseline: 1.4912x; 1.4912x over previous
#include <cuda_runtime.h>
#include <math.h>
#include <stdint.h>

#define NT 1024
#define NV 128
#define NXS 512
#define NVX 65536          // NV*NXS (contraction length of GEMM1)
#define KDIM 257
#define KP 288             // padded KDIM (2 x 144)
#define NXOUT 2048

// -------- scratch (no allocations allowed) --------
__device__ float g_psiT[(size_t)KP * NVX];    // transposed psi * (hx*hv), tf32-rounded
__device__ float g_w[(size_t)NT * KP];        // weights accumulator
__device__ float g_phi[(size_t)KP * NXOUT];   // fourier basis (rows >= 257 zero)

// ============================ helpers ============================
__device__ __forceinline__ uint32_t smem_u32(const void* p) {
    uint32_t a;
    asm("{ .reg .u64 t; cvta.to.shared.u64 t, %1; cvt.u32.u64 %0, t; }" : "=r"(a) : "l"(p));
    return a;
}
__device__ __forceinline__ uint32_t rna_tf32(float x) {
    uint32_t r;
    asm("cvt.rna.tf32.f32 %0, %1;" : "=r"(r) : "f"(x));
    return r;
}
__device__ __forceinline__ void mma_tf32(float* c, const uint32_t* a, uint32_t b0, uint32_t b1) {
    asm volatile(
        "mma.sync.aligned.m16n8k8.row.col.f32.tf32.tf32.f32 "
        "{%0,%1,%2,%3}, {%4,%5,%6,%7}, {%8,%9}, {%0,%1,%2,%3};"
        : "+f"(c[0]), "+f"(c[1]), "+f"(c[2]), "+f"(c[3])
        : "r"(a[0]), "r"(a[1]), "r"(a[2]), "r"(a[3]), "r"(b0), "r"(b1));
}
__device__ __forceinline__ void cp_async16(uint32_t dst, const void* src) {
    asm volatile("cp.async.cg.shared.global [%0], [%1], 16;" :: "r"(dst), "l"(src) : "memory");
}
__device__ __forceinline__ void cp_commit() { asm volatile("cp.async.commit_group;" ::: "memory"); }
__device__ __forceinline__ void cp_wait0()  { asm volatile("cp.async.wait_group 0;" ::: "memory"); }
__device__ __forceinline__ void cp_wait1()  { asm volatile("cp.async.wait_group 1;" ::: "memory"); }

// ---------------- Psi MLP: (x,v) -> 257, transposed + scaled + tf32-rounded ----------------
__global__ void psi_kernel(const float* __restrict__ xs, const float* __restrict__ vs,
                           const float* __restrict__ W1, const float* __restrict__ b1,
                           const float* __restrict__ W2, const float* __restrict__ b2,
                           const float* __restrict__ W3, const float* __restrict__ b3)
{
    __shared__ float sW1[128];
    __shared__ float sb1[64];
    __shared__ float sW2[64 * 32];
    __shared__ float sb2[32];
    __shared__ float sW3[32 * KDIM];
    __shared__ float sb3[KDIM];

    int tid = threadIdx.x;
    for (int i = tid; i < 128; i += 256)       sW1[i] = W1[i];
    for (int i = tid; i < 64; i += 256)        sb1[i] = b1[i];
    for (int i = tid; i < 64 * 32; i += 256)   sW2[i] = W2[i];
    if (tid < 32)                              sb2[tid] = b2[tid];
    for (int i = tid; i < 32 * KDIM; i += 256) sW3[i] = W3[i];
    for (int i = tid; i < KDIM; i += 256)      sb3[i] = b3[i];
    __syncthreads();

    int p = blockIdx.x * 256 + tid;
    int v = p >> 9;
    int x = p & 511;
    float xin = xs[x];
    float vin = vs[v];
    float scale = (xs[1] - xs[0]) * (vs[1] - vs[0]);   // hx * hv

    float h1[64];
#pragma unroll
    for (int j = 0; j < 64; j++) {
        float s = fmaf(xin, sW1[j], fmaf(vin, sW1[64 + j], sb1[j]));
        h1[j] = fmaxf(s, 0.0f);
    }
    float h2[32];
#pragma unroll
    for (int j = 0; j < 32; j++) {
        float s = sb2[j];
#pragma unroll
        for (int i = 0; i < 64; i++) s = fmaf(h1[i], sW2[i * 32 + j], s);
        h2[j] = fmaxf(s, 0.0f);
    }
    for (int k = 0; k < KDIM; k++) {
        float s = sb3[k];
#pragma unroll
        for (int j = 0; j < 32; j++) s = fmaf(h2[j], sW3[j * KDIM + k], s);
        g_psiT[(size_t)k * NVX + p] = __uint_as_float(rna_tf32(s * scale));
    }
}

// ---------------- zero g_w + padding rows of psiT/phi ----------------
#define ZERO_TOTAL (NT * KP + (KP - KDIM) * NVX + (KP - KDIM) * NXOUT)
__global__ void zero_misc_kernel()
{
    int i = blockIdx.x * 256 + threadIdx.x;
    if (i < NT * KP) { g_w[i] = 0.0f; return; }
    i -= NT * KP;
    if (i < (KP - KDIM) * NVX) { g_psiT[(size_t)KDIM * NVX + i] = 0.0f; return; }
    i -= (KP - KDIM) * NVX;
    if (i < (KP - KDIM) * NXOUT) g_phi[(size_t)KDIM * NXOUT + i] = 0.0f;
}

// ---------------- phi table: (K, Nx_out) ----------------
__global__ void phi_kernel(const float* __restrict__ x_out, const float* __restrict__ xs)
{
    int idx = blockIdx.x * 256 + threadIdx.x;
    if (idx >= KDIM * NXOUT) return;
    int r = idx / NXOUT;
    int x = idx - r * NXOUT;
    float w = (2.0f * 3.14159265358979323846f) / (xs[NXS - 1] - xs[0]);
    float xo = x_out[x];
    float val;
    if (r < 128) val = sinf((float)(r + 1) * w * xo);
    else         val = cosf((float)(r - 128) * w * xo);
    g_phi[idx] = val;
}

// ---------------- GEMM1 via mma.sync tf32, 3-stage cp.async ----------------
// C (1024 x 288) += f (1024 x 65536) @ psiT^T
// CTA tile 256x144, BK=32, 256 threads: warps 4(M) x 2(N), warp tile 64x72.
// Split-K: 18 uneven chunks (17 x 3648 + 1 x 3520), grid 2 x 4 x 18 = 144 CTAs.
#define BM 256
#define BN 144
#define BK 32
#define SPLITS 18
#define CHUNK 3648              // 114 * 32 ; last chunk = 3520 = 110 * 32
#define SA 36                   // bank = (4q+j)%32 -> conflict-free
#define SB 36
#define A_FLOATS (BM * SA)      // 9216
#define B_FLOATS (BN * SB)      // 5184
#define STAGE_FLOATS (A_FLOATS + B_FLOATS)          // 14400
#define SMEM_FLOATS (3 * STAGE_FLOATS)              // 43200 floats = 172800 B
#define B_VEC (BN * 8)          // 1152 float4 per B tile

__global__ void __launch_bounds__(256, 1) gemm1_mma(const float* __restrict__ f)
{
    extern __shared__ __align__(16) float sm[];
    uint32_t sm_b = smem_u32(sm);

    const int tid = threadIdx.x;
    const int lane = tid & 31;
    const int warp = tid >> 5;
    const int wm = warp & 3;                 // 0..3 (M)
    const int wn = warp >> 2;                // 0..1 (N)
    const int q = lane >> 2, j = lane & 3;

    const int row0 = blockIdx.y * BM;
    const int col0 = blockIdx.x * BN;
    const int z = blockIdx.z;
    const size_t kb0 = (size_t)z * CHUNK;
    const int NIT = (z == SPLITS - 1) ? (NVX - (SPLITS - 1) * CHUNK) / BK : CHUNK / BK;

    const int lrow = tid >> 3;               // 0..31 (A: 32 rows per pass, 8 passes)
    const int loct = tid & 7;                // 0..7

    float acc[4][9][4];
#pragma unroll
    for (int a = 0; a < 4; a++)
#pragma unroll
        for (int b = 0; b < 9; b++)
#pragma unroll
            for (int c = 0; c < 4; c++) acc[a][b][c] = 0.0f;

    // per-stage base addresses
    uint32_t a_u32[3], b_u32[3];
    const float* As[3];
    const float* Bs[3];
#pragma unroll
    for (int s = 0; s < 3; s++) {
        a_u32[s] = sm_b + (uint32_t)(s * STAGE_FLOATS) * 4u;
        b_u32[s] = a_u32[s] + (uint32_t)A_FLOATS * 4u;
        As[s] = sm + s * STAGE_FLOATS;
        Bs[s] = sm + s * STAGE_FLOATS + A_FLOATS;
    }

    // ---- load one stage (A raw f, B psiT) ----
    auto load_stage = [&](int s, size_t kb) {
        // A: 2048 float4 -> 8 per thread
#pragma unroll
        for (int i = 0; i < 8; i++) {
            int r = lrow + i * 32;
            cp_async16(a_u32[s] + (uint32_t)(r * SA + loct * 4) * 4,
                       f + (size_t)(row0 + r) * NVX + kb + loct * 4);
        }
        // B: 1152 float4
#pragma unroll
        for (int p = 0; p < 5; p++) {
            int idx = tid + p * 256;
            if (idx < B_VEC) {
                int r = idx >> 3, o = idx & 7;
                cp_async16(b_u32[s] + (uint32_t)(r * SB + o * 4) * 4,
                           g_psiT + (size_t)(col0 + r) * NVX + kb + o * 4);
            }
        }
        cp_commit();
    };

    // ---- prologue: stages 0 and 1 in flight ----
    load_stage(0, kb0);
    load_stage(1, kb0 + BK);

    int s = 0;
    for (int it = 0; it < NIT; ++it) {
        // wait for stage s data
        if (it + 1 < NIT) cp_wait1(); else cp_wait0();
        __syncthreads();   // all copies visible to all threads; stage (s+2)%3 free

        // issue loads for stage s+2
        if (it + 2 < NIT)
            load_stage((s + 2 >= 3) ? s - 1 : s + 2, kb0 + (size_t)(it + 2) * BK);

        // ---- compute 4 k8-steps on stage s ----
        const float* Ab = As[s];
        const float* Bb = Bs[s];
#pragma unroll
        for (int kk = 0; kk < 4; kk++) {
            uint32_t afr[4][4];
#pragma unroll
            for (int mt = 0; mt < 4; mt++) {
                const float* ap = Ab + (wm * 64 + mt * 16 + q) * SA + kk * 8 + j;
                afr[mt][0] = __float_as_uint(ap[0]);
                afr[mt][1] = __float_as_uint(ap[8 * SA]);
                afr[mt][2] = __float_as_uint(ap[4]);
                afr[mt][3] = __float_as_uint(ap[8 * SA + 4]);
            }
#pragma unroll
            for (int nt = 0; nt < 9; nt++) {
                const float* bp = Bb + (wn * 72 + nt * 8 + q) * SB + kk * 8 + j;
                uint32_t b0 = __float_as_uint(bp[0]);
                uint32_t b1 = __float_as_uint(bp[4]);
#pragma unroll
                for (int mt = 0; mt < 4; mt++)
                    mma_tf32(acc[mt][nt], afr[mt], b0, b1);
            }
        }
        __syncthreads();   // consumption of stage s done before it is overwritten
        s = (s + 1 >= 3) ? 0 : s + 1;
    }

    // ---- epilogue: atomic accumulate into g_w ----
#pragma unroll
    for (int mt = 0; mt < 4; mt++) {
        int r0 = row0 + wm * 64 + mt * 16 + q;
#pragma unroll
        for (int nt = 0; nt < 9; nt++) {
            int c0 = col0 + wn * 72 + nt * 8 + 2 * j;
            atomicAdd(&g_w[(size_t)r0 * KP + c0],           acc[mt][nt][0]);
            atomicAdd(&g_w[(size_t)r0 * KP + c0 + 1],       acc[mt][nt][1]);
            atomicAdd(&g_w[(size_t)(r0 + 8) * KP + c0],     acc[mt][nt][2]);
            atomicAdd(&g_w[(size_t)(r0 + 8) * KP + c0 + 1], acc[mt][nt][3]);
        }
    }
}

// ---------------- GEMM2: out = g_w (NT x KP) @ g_phi (KP x NXOUT) ----------------
#define G2_BM 64
#define G2_BN 64
#define G2_BK 16

__global__ void gemm2_kernel(float* __restrict__ out)
{
    __shared__ __align__(16) float As2[G2_BK][G2_BM + 4];
    __shared__ __align__(16) float Bs2[G2_BK][G2_BN];

    int nt = blockIdx.x;
    int mt = blockIdx.y;
    int tid = threadIdx.x;
    int tx = tid & 15;
    int ty = tid >> 4;

    int row0 = mt * G2_BM;
    int col0 = nt * G2_BN;

    float acc[4][4];
#pragma unroll
    for (int r = 0; r < 4; r++)
#pragma unroll
        for (int c = 0; c < 4; c++) acc[r][c] = 0.0f;

    for (int kc = 0; kc < KP; kc += G2_BK) {
#pragma unroll
        for (int i = 0; i < 4; i++) {
            int l = tid + i * 256;
            int mrow = l >> 4;
            int kk = l & 15;
            As2[kk][mrow] = g_w[(size_t)(row0 + mrow) * KP + kc + kk];
        }
#pragma unroll
        for (int i = 0; i < 4; i++) {
            int l = tid + i * 256;
            int kk = l >> 6;
            int n = l & 63;
            Bs2[kk][n] = g_phi[(size_t)(kc + kk) * NXOUT + col0 + n];
        }
        __syncthreads();
#pragma unroll
        for (int kk = 0; kk < G2_BK; kk++) {
            float4 a = *(const float4*)&As2[kk][ty * 4];
            float4 b = *(const float4*)&Bs2[kk][tx * 4];
            float avv[4] = {a.x, a.y, a.z, a.w};
            float bvv[4] = {b.x, b.y, b.z, b.w};
#pragma unroll
            for (int r = 0; r < 4; r++)
#pragma unroll
                for (int c = 0; c < 4; c++)
                    acc[r][c] = fmaf(avv[r], bvv[c], acc[r][c]);
        }
        __syncthreads();
    }

#pragma unroll
    for (int r = 0; r < 4; r++) {
        int gm = row0 + ty * 4 + r;
#pragma unroll
        for (int c = 0; c < 4; c++) {
            int gn = col0 + tx * 4 + c;
            out[(size_t)gm * NXOUT + gn] = acc[r][c];
        }
    }
}

extern "C" void kernel_launch(void* const* d_in, const int* in_sizes, int n_in,
                              void* d_out, int out_size)
{
    const float* x_out = (const float*)d_in[0];
    const float* f     = (const float*)d_in[1];
    const float* xs    = (const float*)d_in[2];
    const float* vs    = (const float*)d_in[3];
    const float* W1    = (const float*)d_in[4];
    const float* b1    = (const float*)d_in[5];
    const float* W2    = (const float*)d_in[6];
    const float* b2    = (const float*)d_in[7];
    const float* W3    = (const float*)d_in[8];
    const float* b3    = (const float*)d_in[9];
    float* out = (float*)d_out;

    static int smem_set = 0;
    if (!smem_set) {
        cudaFuncSetAttribute(gemm1_mma, cudaFuncAttributeMaxDynamicSharedMemorySize,
                             SMEM_FLOATS * 4);
        smem_set = 1;
    }

    psi_kernel<<<NVX / 256, 256>>>(xs, vs, W1, b1, W2, b2, W3, b3);
    zero_misc_kernel<<<(ZERO_TOTAL + 255) / 256, 256>>>();
    phi_kernel<<<(KDIM * NXOUT + 255) / 256, 256>>>(x_out, xs);
    {
        dim3 grid(2, 4, SPLITS);   // N tiles, M tiles, split-K
        gemm1_mma<<<grid, 256, SMEM_FLOATS * 4>>>(f);
    }
    {
        dim3 grid(NXOUT / G2_BN, NT / G2_BM);
        gemm2_kernel<<<grid, 256>>>(out);
    }
}

// round 8
// speedup vs baseline: 1.5696x; 1.0526x over previous
#include <cuda_runtime.h>
#include <math.h>
#include <stdint.h>

#define NT 1024
#define NV 128
#define NXS 512
#define NVX 65536          // NV*NXS (contraction length of GEMM1)
#define KDIM 257
#define KP 288             // padded KDIM (2 x 144)
#define NXOUT 2048

// -------- scratch (no allocations allowed) --------
__device__ float g_psiT[(size_t)KP * NVX];    // transposed psi * (hx*hv), tf32-rounded
__device__ float g_w[(size_t)NT * KP];        // weights accumulator
__device__ float g_phi[(size_t)KP * NXOUT];   // fourier basis (rows >= 257 zero)

// ============================ helpers ============================
__device__ __forceinline__ uint32_t smem_u32(const void* p) {
    uint32_t a;
    asm("{ .reg .u64 t; cvta.to.shared.u64 t, %1; cvt.u32.u64 %0, t; }" : "=r"(a) : "l"(p));
    return a;
}
__device__ __forceinline__ uint32_t rna_tf32(float x) {
    uint32_t r;
    asm("cvt.rna.tf32.f32 %0, %1;" : "=r"(r) : "f"(x));
    return r;
}
__device__ __forceinline__ void mma_tf32(float* c, const uint32_t* a, uint32_t b0, uint32_t b1) {
    asm volatile(
        "mma.sync.aligned.m16n8k8.row.col.f32.tf32.tf32.f32 "
        "{%0,%1,%2,%3}, {%4,%5,%6,%7}, {%8,%9}, {%0,%1,%2,%3};"
        : "+f"(c[0]), "+f"(c[1]), "+f"(c[2]), "+f"(c[3])
        : "r"(a[0]), "r"(a[1]), "r"(a[2]), "r"(a[3]), "r"(b0), "r"(b1));
}
__device__ __forceinline__ void ldsm_x4(uint32_t& r0, uint32_t& r1, uint32_t& r2, uint32_t& r3,
                                        uint32_t a) {
    asm volatile("ldmatrix.sync.aligned.m8n8.x4.shared.b16 {%0,%1,%2,%3}, [%4];"
                 : "=r"(r0), "=r"(r1), "=r"(r2), "=r"(r3) : "r"(a));
}
__device__ __forceinline__ void ldsm_x2(uint32_t& r0, uint32_t& r1, uint32_t a) {
    asm volatile("ldmatrix.sync.aligned.m8n8.x2.shared.b16 {%0,%1}, [%2];"
                 : "=r"(r0), "=r"(r1) : "r"(a));
}
__device__ __forceinline__ void cp_async16(uint32_t dst, const void* src) {
    asm volatile("cp.async.cg.shared.global [%0], [%1], 16;" :: "r"(dst), "l"(src) : "memory");
}
__device__ __forceinline__ void cp_commit() { asm volatile("cp.async.commit_group;" ::: "memory"); }
__device__ __forceinline__ void cp_wait0()  { asm volatile("cp.async.wait_group 0;" ::: "memory"); }
__device__ __forceinline__ void cp_wait1()  { asm volatile("cp.async.wait_group 1;" ::: "memory"); }

// ---------------- Psi MLP: (x,v) -> 257, transposed + scaled + tf32-rounded ----------------
__global__ void psi_kernel(const float* __restrict__ xs, const float* __restrict__ vs,
                           const float* __restrict__ W1, const float* __restrict__ b1,
                           const float* __restrict__ W2, const float* __restrict__ b2,
                           const float* __restrict__ W3, const float* __restrict__ b3)
{
    __shared__ float sW1[128];
    __shared__ float sb1[64];
    __shared__ float sW2[64 * 32];
    __shared__ float sb2[32];
    __shared__ float sW3[32 * KDIM];
    __shared__ float sb3[KDIM];

    int tid = threadIdx.x;
    for (int i = tid; i < 128; i += 256)       sW1[i] = W1[i];
    for (int i = tid; i < 64; i += 256)        sb1[i] = b1[i];
    for (int i = tid; i < 64 * 32; i += 256)   sW2[i] = W2[i];
    if (tid < 32)                              sb2[tid] = b2[tid];
    for (int i = tid; i < 32 * KDIM; i += 256) sW3[i] = W3[i];
    for (int i = tid; i < KDIM; i += 256)      sb3[i] = b3[i];
    __syncthreads();

    int p = blockIdx.x * 256 + tid;
    int v = p >> 9;
    int x = p & 511;
    float xin = xs[x];
    float vin = vs[v];
    float scale = (xs[1] - xs[0]) * (vs[1] - vs[0]);   // hx * hv

    float h1[64];
#pragma unroll
    for (int j = 0; j < 64; j++) {
        float s = fmaf(xin, sW1[j], fmaf(vin, sW1[64 + j], sb1[j]));
        h1[j] = fmaxf(s, 0.0f);
    }
    float h2[32];
#pragma unroll
    for (int j = 0; j < 32; j++) {
        float s = sb2[j];
#pragma unroll
        for (int i = 0; i < 64; i++) s = fmaf(h1[i], sW2[i * 32 + j], s);
        h2[j] = fmaxf(s, 0.0f);
    }
    for (int k = 0; k < KDIM; k++) {
        float s = sb3[k];
#pragma unroll
        for (int j = 0; j < 32; j++) s = fmaf(h2[j], sW3[j * KDIM + k], s);
        g_psiT[(size_t)k * NVX + p] = __uint_as_float(rna_tf32(s * scale));
    }
}

// ---------------- zero g_w + padding rows of psiT/phi ----------------
#define ZERO_TOTAL (NT * KP + (KP - KDIM) * NVX + (KP - KDIM) * NXOUT)
__global__ void zero_misc_kernel()
{
    int i = blockIdx.x * 256 + threadIdx.x;
    if (i < NT * KP) { g_w[i] = 0.0f; return; }
    i -= NT * KP;
    if (i < (KP - KDIM) * NVX) { g_psiT[(size_t)KDIM * NVX + i] = 0.0f; return; }
    i -= (KP - KDIM) * NVX;
    if (i < (KP - KDIM) * NXOUT) g_phi[(size_t)KDIM * NXOUT + i] = 0.0f;
}

// ---------------- phi table: (K, Nx_out) ----------------
__global__ void phi_kernel(const float* __restrict__ x_out, const float* __restrict__ xs)
{
    int idx = blockIdx.x * 256 + threadIdx.x;
    if (idx >= KDIM * NXOUT) return;
    int r = idx / NXOUT;
    int x = idx - r * NXOUT;
    float w = (2.0f * 3.14159265358979323846f) / (xs[NXS - 1] - xs[0]);
    float xo = x_out[x];
    float val;
    if (r < 128) val = sinf((float)(r + 1) * w * xo);
    else         val = cosf((float)(r - 128) * w * xo);
    g_phi[idx] = val;
}

// ---------------- GEMM1 via mma.sync tf32, 3-stage cp.async, ldmatrix fragments ----------------
// C (1024 x 288) += f (1024 x 65536) @ psiT^T
// CTA tile 256x144, BK=32, 256 threads: warps 4(M) x 2(N), warp tile 64x72.
// Split-K: 18 uneven chunks (17 x 3648 + 1 x 3520), grid 2 x 4 x 18 = 144 CTAs.
#define BM 256
#define BN 144
#define BK 32
#define SPLITS 18
#define CHUNK 3648              // 114 * 32 ; last chunk = 3520 = 110 * 32
#define SA 36                   // bank = (4q+j)%32 -> conflict-free; row*SA*4 = 144*row, 16B-aligned
#define SB 36
#define A_FLOATS (BM * SA)      // 9216
#define B_FLOATS (BN * SB)      // 5184
#define STAGE_FLOATS (A_FLOATS + B_FLOATS)          // 14400
#define SMEM_FLOATS (3 * STAGE_FLOATS)              // 43200 floats = 172800 B
#define B_VEC (BN * 8)          // 1152 float4 per B tile

__global__ void __launch_bounds__(256, 1) gemm1_mma(const float* __restrict__ f)
{
    extern __shared__ __align__(16) float sm[];
    uint32_t sm_b = smem_u32(sm);

    const int tid = threadIdx.x;
    const int lane = tid & 31;
    const int warp = tid >> 5;
    const int wm = warp & 3;                 // 0..3 (M)
    const int wn = warp >> 2;                // 0..1 (N)
    const int q = lane >> 2, j = lane & 3;

    const int row0 = blockIdx.y * BM;
    const int col0 = blockIdx.x * BN;
    const int z = blockIdx.z;
    const size_t kb0 = (size_t)z * CHUNK;
    const int NIT = (z == SPLITS - 1) ? (NVX - (SPLITS - 1) * CHUNK) / BK : CHUNK / BK;

    const int lrow = tid >> 3;               // 0..31 (A: 32 rows per pass, 8 passes)
    const int loct = tid & 7;                // 0..7

    float acc[4][9][4];
#pragma unroll
    for (int a = 0; a < 4; a++)
#pragma unroll
        for (int b = 0; b < 9; b++)
#pragma unroll
            for (int c = 0; c < 4; c++) acc[a][b][c] = 0.0f;

    // per-stage base addresses
    uint32_t a_u32[3], b_u32[3];
#pragma unroll
    for (int s = 0; s < 3; s++) {
        a_u32[s] = sm_b + (uint32_t)(s * STAGE_FLOATS) * 4u;
        b_u32[s] = a_u32[s] + (uint32_t)A_FLOATS * 4u;
    }

    // ---- ldmatrix lane-address offsets (bytes, within stage) ----
    // A fragment (m16k8 as x4): blocks m0..m3 = lanes 0-7/8-15/16-23/24-31
    //   row_off = (lane&7) + ((lane>>3)&1)*8 ; col_off = (lane>>4)*4
    const int arow = (lane & 7) + ((lane >> 3) & 1) * 8;
    const int acol = (lane >> 4) * 4;
    uint32_t offA[4];
#pragma unroll
    for (int mt = 0; mt < 4; mt++)
        offA[mt] = (uint32_t)(((wm * 64 + mt * 16 + arow) * SA + acol) * 4);

    // B pair fragments (two n8k8 as x4): m0/m1 = nt0 cols j/j+4, m2/m3 = nt1
    //   row_off = (2p + (lane>>4))*8 + (lane&7) ; col_off = ((lane>>3)&1)*4
    const int brow = (lane & 7);
    const int bsel = (lane >> 4);            // 0 or 1: which nt of the pair
    const int bcol = ((lane >> 3) & 1) * 4;
    uint32_t offB[4];
#pragma unroll
    for (int p = 0; p < 4; p++)
        offB[p] = (uint32_t)(((wn * 72 + (2 * p + bsel) * 8 + brow) * SB + bcol) * 4);
    // last B fragment (nt=8) as x2: lanes 0-15, rows 64..71, cols j/j+4
    uint32_t offB2 = (uint32_t)(((wn * 72 + 64 + brow) * SB + bcol) * 4);

    // ---- load one stage (A raw f, B psiT) ----
    auto load_stage = [&](int s, size_t kb) {
#pragma unroll
        for (int i = 0; i < 8; i++) {
            int r = lrow + i * 32;
            cp_async16(a_u32[s] + (uint32_t)(r * SA + loct * 4) * 4,
                       f + (size_t)(row0 + r) * NVX + kb + loct * 4);
        }
#pragma unroll
        for (int p = 0; p < 5; p++) {
            int idx = tid + p * 256;
            if (idx < B_VEC) {
                int r = idx >> 3, o = idx & 7;
                cp_async16(b_u32[s] + (uint32_t)(r * SB + o * 4) * 4,
                           g_psiT + (size_t)(col0 + r) * NVX + kb + o * 4);
            }
        }
        cp_commit();
    };

    // ---- prologue: stages 0 and 1 in flight ----
    load_stage(0, kb0);
    load_stage(1, kb0 + BK);

    int s = 0;
    for (int it = 0; it < NIT; ++it) {
        if (it + 1 < NIT) cp_wait1(); else cp_wait0();
        __syncthreads();

        if (it + 2 < NIT)
            load_stage((s + 2 >= 3) ? s - 1 : s + 2, kb0 + (size_t)(it + 2) * BK);

        // ---- compute 4 k8-steps on stage s ----
        const uint32_t aS = a_u32[s];
        const uint32_t bS = b_u32[s];
#pragma unroll
        for (int kk = 0; kk < 4; kk++) {
            uint32_t afr[4][4];
#pragma unroll
            for (int mt = 0; mt < 4; mt++)
                ldsm_x4(afr[mt][0], afr[mt][1], afr[mt][2], afr[mt][3],
                        aS + offA[mt] + kk * 32);
            uint32_t bfr[9][2];
#pragma unroll
            for (int p = 0; p < 4; p++)
                ldsm_x4(bfr[2 * p][0], bfr[2 * p][1], bfr[2 * p + 1][0], bfr[2 * p + 1][1],
                        bS + offB[p] + kk * 32);
            ldsm_x2(bfr[8][0], bfr[8][1], bS + offB2 + kk * 32);
#pragma unroll
            for (int nt = 0; nt < 9; nt++)
#pragma unroll
                for (int mt = 0; mt < 4; mt++)
                    mma_tf32(acc[mt][nt], afr[mt], bfr[nt][0], bfr[nt][1]);
        }
        __syncthreads();
        s = (s + 1 >= 3) ? 0 : s + 1;
    }

    // ---- epilogue: atomic accumulate into g_w ----
#pragma unroll
    for (int mt = 0; mt < 4; mt++) {
        int r0 = row0 + wm * 64 + mt * 16 + q;
#pragma unroll
        for (int nt = 0; nt < 9; nt++) {
            int c0 = col0 + wn * 72 + nt * 8 + 2 * j;
            atomicAdd(&g_w[(size_t)r0 * KP + c0],           acc[mt][nt][0]);
            atomicAdd(&g_w[(size_t)r0 * KP + c0 + 1],       acc[mt][nt][1]);
            atomicAdd(&g_w[(size_t)(r0 + 8) * KP + c0],     acc[mt][nt][2]);
            atomicAdd(&g_w[(size_t)(r0 + 8) * KP + c0 + 1], acc[mt][nt][3]);
        }
    }
}

// ---------------- GEMM2: out = g_w (NT x KP) @ g_phi (KP x NXOUT) ----------------
#define G2_BM 64
#define G2_BN 64
#define G2_BK 16

__global__ void gemm2_kernel(float* __restrict__ out)
{
    __shared__ __align__(16) float As2[G2_BK][G2_BM + 4];
    __shared__ __align__(16) float Bs2[G2_BK][G2_BN];

    int nt = blockIdx.x;
    int mt = blockIdx.y;
    int tid = threadIdx.x;
    int tx = tid & 15;
    int ty = tid >> 4;

    int row0 = mt * G2_BM;
    int col0 = nt * G2_BN;

    float acc[4][4];
#pragma unroll
    for (int r = 0; r < 4; r++)
#pragma unroll
        for (int c = 0; c < 4; c++) acc[r][c] = 0.0f;

    for (int kc = 0; kc < KP; kc += G2_BK) {
#pragma unroll
        for (int i = 0; i < 4; i++) {
            int l = tid + i * 256;
            int mrow = l >> 4;
            int kk = l & 15;
            As2[kk][mrow] = g_w[(size_t)(row0 + mrow) * KP + kc + kk];
        }
#pragma unroll
        for (int i = 0; i < 4; i++) {
            int l = tid + i * 256;
            int kk = l >> 6;
            int n = l & 63;
            Bs2[kk][n] = g_phi[(size_t)(kc + kk) * NXOUT + col0 + n];
        }
        __syncthreads();
#pragma unroll
        for (int kk = 0; kk < G2_BK; kk++) {
            float4 a = *(const float4*)&As2[kk][ty * 4];
            float4 b = *(const float4*)&Bs2[kk][tx * 4];
            float avv[4] = {a.x, a.y, a.z, a.w};
            float bvv[4] = {b.x, b.y, b.z, b.w};
#pragma unroll
            for (int r = 0; r < 4; r++)
#pragma unroll
                for (int c = 0; c < 4; c++)
                    acc[r][c] = fmaf(avv[r], bvv[c], acc[r][c]);
        }
        __syncthreads();
    }

#pragma unroll
    for (int r = 0; r < 4; r++) {
        int gm = row0 + ty * 4 + r;
#pragma unroll
        for (int c = 0; c < 4; c++) {
            int gn = col0 + tx * 4 + c;
            out[(size_t)gm * NXOUT + gn] = acc[r][c];
        }
    }
}

extern "C" void kernel_launch(void* const* d_in, const int* in_sizes, int n_in,
                              void* d_out, int out_size)
{
    const float* x_out = (const float*)d_in[0];
    const float* f     = (const float*)d_in[1];
    const float* xs    = (const float*)d_in[2];
    const float* vs    = (const float*)d_in[3];
    const float* W1    = (const float*)d_in[4];
    const float* b1    = (const float*)d_in[5];
    const float* W2    = (const float*)d_in[6];
    const float* b2    = (const float*)d_in[7];
    const float* W3    = (const float*)d_in[8];
    const float* b3    = (const float*)d_in[9];
    float* out = (float*)d_out;

    static int smem_set = 0;
    if (!smem_set) {
        cudaFuncSetAttribute(gemm1_mma, cudaFuncAttributeMaxDynamicSharedMemorySize,
                             SMEM_FLOATS * 4);
        smem_set = 1;
    }

    psi_kernel<<<NVX / 256, 256>>>(xs, vs, W1, b1, W2, b2, W3, b3);
    zero_misc_kernel<<<(ZERO_TOTAL + 255) / 256, 256>>>();
    phi_kernel<<<(KDIM * NXOUT + 255) / 256, 256>>>(x_out, xs);
    {
        dim3 grid(2, 4, SPLITS);   // N tiles, M tiles, split-K
        gemm1_mma<<<grid, 256, SMEM_FLOATS * 4>>>(f);
    }
    {
        dim3 grid(NXOUT / G2_BN, NT / G2_BM);
        gemm2_kernel<<<grid, 256>>>(out);
    }
}

// round 9
// speedup vs baseline: 1.5975x; 1.0177x over previous
#include <cuda_runtime.h>
#include <math.h>
#include <stdint.h>

#define NT 1024
#define NV 128
#define NXS 512
#define NVX 65536          // NV*NXS (contraction length of GEMM1)
#define KDIM 257
#define KP 288             // padded KDIM (2 x 144)
#define NXOUT 2048

// -------- scratch (no allocations allowed) --------
__device__ float g_psiT[(size_t)KP * NVX];    // transposed psi * (hx*hv), tf32-rounded
__device__ float g_w[(size_t)NT * KP];        // weights accumulator
__device__ float g_phi[(size_t)KP * NXOUT];   // fourier basis (rows >= 257 zero)

// ============================ helpers ============================
__device__ __forceinline__ uint32_t smem_u32(const void* p) {
    uint32_t a;
    asm("{ .reg .u64 t; cvta.to.shared.u64 t, %1; cvt.u32.u64 %0, t; }" : "=r"(a) : "l"(p));
    return a;
}
__device__ __forceinline__ uint32_t rna_tf32(float x) {
    uint32_t r;
    asm("cvt.rna.tf32.f32 %0, %1;" : "=r"(r) : "f"(x));
    return r;
}
__device__ __forceinline__ void mma_tf32(float* c, const uint32_t* a, uint32_t b0, uint32_t b1) {
    asm volatile(
        "mma.sync.aligned.m16n8k8.row.col.f32.tf32.tf32.f32 "
        "{%0,%1,%2,%3}, {%4,%5,%6,%7}, {%8,%9}, {%0,%1,%2,%3};"
        : "+f"(c[0]), "+f"(c[1]), "+f"(c[2]), "+f"(c[3])
        : "r"(a[0]), "r"(a[1]), "r"(a[2]), "r"(a[3]), "r"(b0), "r"(b1));
}
__device__ __forceinline__ void ldsm_x4(uint32_t& r0, uint32_t& r1, uint32_t& r2, uint32_t& r3,
                                        uint32_t a) {
    asm volatile("ldmatrix.sync.aligned.m8n8.x4.shared.b16 {%0,%1,%2,%3}, [%4];"
                 : "=r"(r0), "=r"(r1), "=r"(r2), "=r"(r3) : "r"(a));
}
__device__ __forceinline__ void cp_async16(uint32_t dst, const void* src) {
    asm volatile("cp.async.cg.shared.global [%0], [%1], 16;" :: "r"(dst), "l"(src) : "memory");
}
__device__ __forceinline__ void cp_commit() { asm volatile("cp.async.commit_group;" ::: "memory"); }
__device__ __forceinline__ void cp_wait0()  { asm volatile("cp.async.wait_group 0;" ::: "memory"); }
__device__ __forceinline__ void cp_wait1()  { asm volatile("cp.async.wait_group 1;" ::: "memory"); }

// ---------------- Psi MLP: (x,v) -> 257, transposed + scaled + tf32-rounded ----------------
__global__ void psi_kernel(const float* __restrict__ xs, const float* __restrict__ vs,
                           const float* __restrict__ W1, const float* __restrict__ b1,
                           const float* __restrict__ W2, const float* __restrict__ b2,
                           const float* __restrict__ W3, const float* __restrict__ b3)
{
    __shared__ float sW1[128];
    __shared__ float sb1[64];
    __shared__ float sW2[64 * 32];
    __shared__ float sb2[32];
    __shared__ float sW3[32 * KDIM];
    __shared__ float sb3[KDIM];

    int tid = threadIdx.x;
    for (int i = tid; i < 128; i += 256)       sW1[i] = W1[i];
    for (int i = tid; i < 64; i += 256)        sb1[i] = b1[i];
    for (int i = tid; i < 64 * 32; i += 256)   sW2[i] = W2[i];
    if (tid < 32)                              sb2[tid] = b2[tid];
    for (int i = tid; i < 32 * KDIM; i += 256) sW3[i] = W3[i];
    for (int i = tid; i < KDIM; i += 256)      sb3[i] = b3[i];
    __syncthreads();

    int p = blockIdx.x * 256 + tid;
    int v = p >> 9;
    int x = p & 511;
    float xin = xs[x];
    float vin = vs[v];
    float scale = (xs[1] - xs[0]) * (vs[1] - vs[0]);   // hx * hv

    float h1[64];
#pragma unroll
    for (int j = 0; j < 64; j++) {
        float s = fmaf(xin, sW1[j], fmaf(vin, sW1[64 + j], sb1[j]));
        h1[j] = fmaxf(s, 0.0f);
    }
    float h2[32];
#pragma unroll
    for (int j = 0; j < 32; j++) {
        float s = sb2[j];
#pragma unroll
        for (int i = 0; i < 64; i++) s = fmaf(h1[i], sW2[i * 32 + j], s);
        h2[j] = fmaxf(s, 0.0f);
    }
    for (int k = 0; k < KDIM; k++) {
        float s = sb3[k];
#pragma unroll
        for (int j = 0; j < 32; j++) s = fmaf(h2[j], sW3[j * KDIM + k], s);
        g_psiT[(size_t)k * NVX + p] = __uint_as_float(rna_tf32(s * scale));
    }
}

// ---------------- zero g_w + padding rows of psiT/phi ----------------
#define ZERO_TOTAL (NT * KP + (KP - KDIM) * NVX + (KP - KDIM) * NXOUT)
__global__ void zero_misc_kernel()
{
    int i = blockIdx.x * 256 + threadIdx.x;
    if (i < NT * KP) { g_w[i] = 0.0f; return; }
    i -= NT * KP;
    if (i < (KP - KDIM) * NVX) { g_psiT[(size_t)KDIM * NVX + i] = 0.0f; return; }
    i -= (KP - KDIM) * NVX;
    if (i < (KP - KDIM) * NXOUT) g_phi[(size_t)KDIM * NXOUT + i] = 0.0f;
}

// ---------------- phi table: (K, Nx_out) ----------------
__global__ void phi_kernel(const float* __restrict__ x_out, const float* __restrict__ xs)
{
    int idx = blockIdx.x * 256 + threadIdx.x;
    if (idx >= KDIM * NXOUT) return;
    int r = idx / NXOUT;
    int x = idx - r * NXOUT;
    float w = (2.0f * 3.14159265358979323846f) / (xs[NXS - 1] - xs[0]);
    float xo = x_out[x];
    float val;
    if (r < 128) val = sinf((float)(r + 1) * w * xo);
    else         val = cosf((float)(r - 128) * w * xo);
    g_phi[idx] = val;
}

// ---------------- GEMM1: mma.sync tf32, 3-stage cp.async, ldmatrix, 12 warps ----------------
// C (1024 x 288) += f (1024 x 65536) @ psiT^T
// CTA tile 256x144, BK=32, 384 threads: warps 4(M) x 3(N), warp tile 64x48.
// Split-K: 18 uneven chunks (17 x 3648 + 1 x 3520), grid 2 x 4 x 18 = 144 CTAs.
#define BM 256
#define BN 144
#define BK 32
#define NTHREADS 384
#define SPLITS 18
#define CHUNK 3648              // 114 * 32 ; last chunk = 3520 = 110 * 32
#define SA 36                   // bank = (4*row + j) % 32 -> conflict-free; 144B rows, 16B-aligned
#define SB 36
#define A_FLOATS (BM * SA)      // 9216
#define B_FLOATS (BN * SB)      // 5184
#define STAGE_FLOATS (A_FLOATS + B_FLOATS)          // 14400
#define SMEM_FLOATS (3 * STAGE_FLOATS)              // 43200 floats = 172800 B
#define A_VEC (BM * 8)          // 2048 float4 per A tile
#define B_VEC (BN * 8)          // 1152 float4 per B tile

__global__ void __launch_bounds__(NTHREADS, 1) gemm1_mma(const float* __restrict__ f)
{
    extern __shared__ __align__(16) float sm[];
    uint32_t sm_b = smem_u32(sm);

    const int tid = threadIdx.x;
    const int lane = tid & 31;
    const int warp = tid >> 5;               // 0..11
    const int wm = warp & 3;                 // 0..3 (M)
    const int wn = warp >> 2;                // 0..2 (N)
    const int q = lane >> 2, j = lane & 3;

    const int row0 = blockIdx.y * BM;
    const int col0 = blockIdx.x * BN;
    const int z = blockIdx.z;
    const size_t kb0 = (size_t)z * CHUNK;
    const int NIT = (z == SPLITS - 1) ? (NVX - (SPLITS - 1) * CHUNK) / BK : CHUNK / BK;

    float acc[4][6][4];
#pragma unroll
    for (int a = 0; a < 4; a++)
#pragma unroll
        for (int b = 0; b < 6; b++)
#pragma unroll
            for (int c = 0; c < 4; c++) acc[a][b][c] = 0.0f;

    // per-stage base addresses
    uint32_t a_u32[3], b_u32[3];
#pragma unroll
    for (int s = 0; s < 3; s++) {
        a_u32[s] = sm_b + (uint32_t)(s * STAGE_FLOATS) * 4u;
        b_u32[s] = a_u32[s] + (uint32_t)A_FLOATS * 4u;
    }

    // ---- ldmatrix lane-address offsets (bytes, within stage) ----
    // A fragment (m16k8 as x4): row = (lane&7) + ((lane>>3)&1)*8 ; col = (lane>>4)*4
    const int arow = (lane & 7) + ((lane >> 3) & 1) * 8;
    const int acol = (lane >> 4) * 4;
    uint32_t offA[4];
#pragma unroll
    for (int mt = 0; mt < 4; mt++)
        offA[mt] = (uint32_t)(((wm * 64 + mt * 16 + arow) * SA + acol) * 4);

    // B pair fragments (two n8k8 as x4): m0/m1 = nt(2p) cols j/j+4, m2/m3 = nt(2p+1)
    const int brow = (lane & 7);
    const int bsel = (lane >> 4);            // which nt of the pair
    const int bcol = ((lane >> 3) & 1) * 4;
    uint32_t offB[3];
#pragma unroll
    for (int p = 0; p < 3; p++)
        offB[p] = (uint32_t)(((wn * 48 + (2 * p + bsel) * 8 + brow) * SB + bcol) * 4);

    // ---- load one stage (A raw f, B psiT) ----
    auto load_stage = [&](int s, size_t kb) {
        // A: 2048 float4, 384 threads
        for (int idx = tid; idx < A_VEC; idx += NTHREADS) {
            int r = idx >> 3, o = idx & 7;
            cp_async16(a_u32[s] + (uint32_t)(r * SA + o * 4) * 4,
                       f + (size_t)(row0 + r) * NVX + kb + o * 4);
        }
        // B: 1152 float4 = 3 per thread exactly
#pragma unroll
        for (int p = 0; p < 3; p++) {
            int idx = tid + p * NTHREADS;
            int r = idx >> 3, o = idx & 7;
            cp_async16(b_u32[s] + (uint32_t)(r * SB + o * 4) * 4,
                       g_psiT + (size_t)(col0 + r) * NVX + kb + o * 4);
        }
        cp_commit();
    };

    // ---- prologue: stages 0 and 1 in flight ----
    load_stage(0, kb0);
    load_stage(1, kb0 + BK);

    int s = 0;
    for (int it = 0; it < NIT; ++it) {
        if (it + 1 < NIT) cp_wait1(); else cp_wait0();
        __syncthreads();   // single barrier per iter: stage s visible; stage (it-1)%3 reusable

        if (it + 2 < NIT)
            load_stage((s + 2 >= 3) ? s - 1 : s + 2, kb0 + (size_t)(it + 2) * BK);

        // ---- compute 4 k8-steps on stage s ----
        const uint32_t aS = a_u32[s];
        const uint32_t bS = b_u32[s];
#pragma unroll
        for (int kk = 0; kk < 4; kk++) {
            uint32_t afr[4][4];
#pragma unroll
            for (int mt = 0; mt < 4; mt++)
                ldsm_x4(afr[mt][0], afr[mt][1], afr[mt][2], afr[mt][3],
                        aS + offA[mt] + kk * 32);
            uint32_t bfr[6][2];
#pragma unroll
            for (int p = 0; p < 3; p++)
                ldsm_x4(bfr[2 * p][0], bfr[2 * p][1], bfr[2 * p + 1][0], bfr[2 * p + 1][1],
                        bS + offB[p] + kk * 32);
#pragma unroll
            for (int nt = 0; nt < 6; nt++)
#pragma unroll
                for (int mt = 0; mt < 4; mt++)
                    mma_tf32(acc[mt][nt], afr[mt], bfr[nt][0], bfr[nt][1]);
        }
        s = (s + 1 >= 3) ? 0 : s + 1;
    }

    // ---- epilogue: atomic accumulate into g_w ----
#pragma unroll
    for (int mt = 0; mt < 4; mt++) {
        int r0 = row0 + wm * 64 + mt * 16 + q;
#pragma unroll
        for (int nt = 0; nt < 6; nt++) {
            int c0 = col0 + wn * 48 + nt * 8 + 2 * j;
            atomicAdd(&g_w[(size_t)r0 * KP + c0],           acc[mt][nt][0]);
            atomicAdd(&g_w[(size_t)r0 * KP + c0 + 1],       acc[mt][nt][1]);
            atomicAdd(&g_w[(size_t)(r0 + 8) * KP + c0],     acc[mt][nt][2]);
            atomicAdd(&g_w[(size_t)(r0 + 8) * KP + c0 + 1], acc[mt][nt][3]);
        }
    }
}

// ---------------- GEMM2: out = g_w (NT x KP) @ g_phi (KP x NXOUT) ----------------
#define G2_BM 64
#define G2_BN 64
#define G2_BK 16

__global__ void gemm2_kernel(float* __restrict__ out)
{
    __shared__ __align__(16) float As2[G2_BK][G2_BM + 4];
    __shared__ __align__(16) float Bs2[G2_BK][G2_BN];

    int nt = blockIdx.x;
    int mt = blockIdx.y;
    int tid = threadIdx.x;
    int tx = tid & 15;
    int ty = tid >> 4;

    int row0 = mt * G2_BM;
    int col0 = nt * G2_BN;

    float acc[4][4];
#pragma unroll
    for (int r = 0; r < 4; r++)
#pragma unroll
        for (int c = 0; c < 4; c++) acc[r][c] = 0.0f;

    for (int kc = 0; kc < KP; kc += G2_BK) {
#pragma unroll
        for (int i = 0; i < 4; i++) {
            int l = tid + i * 256;
            int mrow = l >> 4;
            int kk = l & 15;
            As2[kk][mrow] = g_w[(size_t)(row0 + mrow) * KP + kc + kk];
        }
#pragma unroll
        for (int i = 0; i < 4; i++) {
            int l = tid + i * 256;
            int kk = l >> 6;
            int n = l & 63;
            Bs2[kk][n] = g_phi[(size_t)(kc + kk) * NXOUT + col0 + n];
        }
        __syncthreads();
#pragma unroll
        for (int kk = 0; kk < G2_BK; kk++) {
            float4 a = *(const float4*)&As2[kk][ty * 4];
            float4 b = *(const float4*)&Bs2[kk][tx * 4];
            float avv[4] = {a.x, a.y, a.z, a.w};
            float bvv[4] = {b.x, b.y, b.z, b.w};
#pragma unroll
            for (int r = 0; r < 4; r++)
#pragma unroll
                for (int c = 0; c < 4; c++)
                    acc[r][c] = fmaf(avv[r], bvv[c], acc[r][c]);
        }
        __syncthreads();
    }

#pragma unroll
    for (int r = 0; r < 4; r++) {
        int gm = row0 + ty * 4 + r;
#pragma unroll
        for (int c = 0; c < 4; c++) {
            int gn = col0 + tx * 4 + c;
            out[(size_t)gm * NXOUT + gn] = acc[r][c];
        }
    }
}

extern "C" void kernel_launch(void* const* d_in, const int* in_sizes, int n_in,
                              void* d_out, int out_size)
{
    const float* x_out = (const float*)d_in[0];
    const float* f     = (const float*)d_in[1];
    const float* xs    = (const float*)d_in[2];
    const float* vs    = (const float*)d_in[3];
    const float* W1    = (const float*)d_in[4];
    const float* b1    = (const float*)d_in[5];
    const float* W2    = (const float*)d_in[6];
    const float* b2    = (const float*)d_in[7];
    const float* W3    = (const float*)d_in[8];
    const float* b3    = (const float*)d_in[9];
    float* out = (float*)d_out;

    static int smem_set = 0;
    if (!smem_set) {
        cudaFuncSetAttribute(gemm1_mma, cudaFuncAttributeMaxDynamicSharedMemorySize,
                             SMEM_FLOATS * 4);
        smem_set = 1;
    }

    psi_kernel<<<NVX / 256, 256>>>(xs, vs, W1, b1, W2, b2, W3, b3);
    zero_misc_kernel<<<(ZERO_TOTAL + 255) / 256, 256>>>();
    phi_kernel<<<(KDIM * NXOUT + 255) / 256, 256>>>(x_out, xs);
    {
        dim3 grid(2, 4, SPLITS);   // N tiles, M tiles, split-K
        gemm1_mma<<<grid, NTHREADS, SMEM_FLOATS * 4>>>(f);
    }
    {
        dim3 grid(NXOUT / G2_BN, NT / G2_BM);
        gemm2_kernel<<<grid, 256>>>(out);
    }
}

// round 10
// speedup vs baseline: 1.7295x; 1.0826x over previous
#include <cuda_runtime.h>
#include <math.h>
#include <stdint.h>

#define NT 1024
#define NV 128
#define NXS 512
#define NVX 65536          // NV*NXS (contraction length of GEMM1)
#define KDIM 257
#define KP 288             // padded KDIM
#define NXOUT 2048

// -------- scratch (no allocations allowed) --------
__device__ float g_psiT[(size_t)KP * NVX];     // transposed psi * (hx*hv), tf32-rounded
__device__ float g_w[(size_t)NT * KP];         // weights accumulator
__device__ float g_phiT[(size_t)NXOUT * KP];   // fourier basis transposed [n][k], tf32-rounded

// ============================ helpers ============================
__device__ __forceinline__ uint32_t smem_u32(const void* p) {
    uint32_t a;
    asm("{ .reg .u64 t; cvta.to.shared.u64 t, %1; cvt.u32.u64 %0, t; }" : "=r"(a) : "l"(p));
    return a;
}
__device__ __forceinline__ uint32_t rna_tf32(float x) {
    uint32_t r;
    asm("cvt.rna.tf32.f32 %0, %1;" : "=r"(r) : "f"(x));
    return r;
}
__device__ __forceinline__ void mma_tf32(float* c, const uint32_t* a, uint32_t b0, uint32_t b1) {
    asm volatile(
        "mma.sync.aligned.m16n8k8.row.col.f32.tf32.tf32.f32 "
        "{%0,%1,%2,%3}, {%4,%5,%6,%7}, {%8,%9}, {%0,%1,%2,%3};"
        : "+f"(c[0]), "+f"(c[1]), "+f"(c[2]), "+f"(c[3])
        : "r"(a[0]), "r"(a[1]), "r"(a[2]), "r"(a[3]), "r"(b0), "r"(b1));
}
__device__ __forceinline__ void ldsm_x4(uint32_t& r0, uint32_t& r1, uint32_t& r2, uint32_t& r3,
                                        uint32_t a) {
    asm volatile("ldmatrix.sync.aligned.m8n8.x4.shared.b16 {%0,%1,%2,%3}, [%4];"
                 : "=r"(r0), "=r"(r1), "=r"(r2), "=r"(r3) : "r"(a));
}
__device__ __forceinline__ void cp_async16(uint32_t dst, const void* src) {
    asm volatile("cp.async.cg.shared.global [%0], [%1], 16;" :: "r"(dst), "l"(src) : "memory");
}
__device__ __forceinline__ void cp_commit() { asm volatile("cp.async.commit_group;" ::: "memory"); }
__device__ __forceinline__ void cp_wait0()  { asm volatile("cp.async.wait_group 0;" ::: "memory"); }
__device__ __forceinline__ void cp_wait1()  { asm volatile("cp.async.wait_group 1;" ::: "memory"); }
__device__ __forceinline__ void cp_wait2()  { asm volatile("cp.async.wait_group 2;" ::: "memory"); }

// ---------------- Psi MLP: (x,v) -> 257, transposed + scaled + tf32-rounded ----------------
__global__ void psi_kernel(const float* __restrict__ xs, const float* __restrict__ vs,
                           const float* __restrict__ W1, const float* __restrict__ b1,
                           const float* __restrict__ W2, const float* __restrict__ b2,
                           const float* __restrict__ W3, const float* __restrict__ b3)
{
    __shared__ float sW1[128];
    __shared__ float sb1[64];
    __shared__ float sW2[64 * 32];
    __shared__ float sb2[32];
    __shared__ float sW3[32 * KDIM];
    __shared__ float sb3[KDIM];

    int tid = threadIdx.x;
    for (int i = tid; i < 128; i += 256)       sW1[i] = W1[i];
    for (int i = tid; i < 64; i += 256)        sb1[i] = b1[i];
    for (int i = tid; i < 64 * 32; i += 256)   sW2[i] = W2[i];
    if (tid < 32)                              sb2[tid] = b2[tid];
    for (int i = tid; i < 32 * KDIM; i += 256) sW3[i] = W3[i];
    for (int i = tid; i < KDIM; i += 256)      sb3[i] = b3[i];
    __syncthreads();

    int p = blockIdx.x * 256 + tid;
    int v = p >> 9;
    int x = p & 511;
    float xin = xs[x];
    float vin = vs[v];
    float scale = (xs[1] - xs[0]) * (vs[1] - vs[0]);   // hx * hv

    float h1[64];
#pragma unroll
    for (int j = 0; j < 64; j++) {
        float s = fmaf(xin, sW1[j], fmaf(vin, sW1[64 + j], sb1[j]));
        h1[j] = fmaxf(s, 0.0f);
    }
    float h2[32];
#pragma unroll
    for (int j = 0; j < 32; j++) {
        float s = sb2[j];
#pragma unroll
        for (int i = 0; i < 64; i++) s = fmaf(h1[i], sW2[i * 32 + j], s);
        h2[j] = fmaxf(s, 0.0f);
    }
    for (int k = 0; k < KDIM; k++) {
        float s = sb3[k];
#pragma unroll
        for (int j = 0; j < 32; j++) s = fmaf(h2[j], sW3[j * KDIM + k], s);
        g_psiT[(size_t)k * NVX + p] = __uint_as_float(rna_tf32(s * scale));
    }
}

// ---------------- zero g_w + padding of psiT/phiT ----------------
#define ZERO_TOTAL (NT * KP + (KP - KDIM) * NVX + NXOUT * (KP - KDIM))
__global__ void zero_misc_kernel()
{
    int i = blockIdx.x * 256 + threadIdx.x;
    if (i < NT * KP) { g_w[i] = 0.0f; return; }
    i -= NT * KP;
    if (i < (KP - KDIM) * NVX) { g_psiT[(size_t)KDIM * NVX + i] = 0.0f; return; }
    i -= (KP - KDIM) * NVX;
    if (i < NXOUT * (KP - KDIM)) {
        int n = i / (KP - KDIM);
        int m = i - n * (KP - KDIM);
        g_phiT[(size_t)n * KP + KDIM + m] = 0.0f;
    }
}

// ---------------- phi table transposed: [Nx_out][KP], tf32-rounded ----------------
__global__ void phi_kernel(const float* __restrict__ x_out, const float* __restrict__ xs)
{
    int idx = blockIdx.x * 256 + threadIdx.x;
    if (idx >= NXOUT * KDIM) return;
    int n = idx / KDIM;
    int k = idx - n * KDIM;
    float w = (2.0f * 3.14159265358979323846f) / (xs[NXS - 1] - xs[0]);
    float xo = x_out[n];
    float val;
    if (k < 128) val = sinf((float)(k + 1) * w * xo);
    else         val = cosf((float)(k - 128) * w * xo);
    g_phiT[(size_t)n * KP + k] = __uint_as_float(rna_tf32(val));
}

// ---------------- GEMM1: mma.sync tf32, 4-stage cp.async, ldmatrix, 12 warps ----------------
// C (1024 x 288) += f (1024 x 65536) @ psiT^T
// CTA tile 256x144, BK=32, 384 threads: warps 4(M) x 3(N), warp tile 64x48.
// Split-K: 18 uneven chunks (17 x 3648 + 1 x 3520), grid 2 x 4 x 18 = 144 CTAs.
#define BM 256
#define BN 144
#define BK 32
#define NTHREADS 384
#define SPLITS 18
#define CHUNK 3648              // 114 * 32 ; last chunk = 3520 = 110 * 32
#define SA 36                   // bank = (4*row + j) % 32 -> conflict-free; 144B rows
#define SB 36
#define A_FLOATS (BM * SA)      // 9216
#define B_FLOATS (BN * SB)      // 5184
#define STAGE_FLOATS (A_FLOATS + B_FLOATS)          // 14400
#define NSTAGE 4
#define SMEM_FLOATS (NSTAGE * STAGE_FLOATS)         // 57600 floats = 230400 B
#define A_VEC (BM * 8)          // 2048 float4 per A tile
#define B_VEC (BN * 8)          // 1152 float4 per B tile

__global__ void __launch_bounds__(NTHREADS, 1) gemm1_mma(const float* __restrict__ f)
{
    extern __shared__ __align__(16) float sm[];
    uint32_t sm_b = smem_u32(sm);

    const int tid = threadIdx.x;
    const int lane = tid & 31;
    const int warp = tid >> 5;               // 0..11
    const int wm = warp & 3;                 // 0..3 (M)
    const int wn = warp >> 2;                // 0..2 (N)
    const int q = lane >> 2, j = lane & 3;

    const int row0 = blockIdx.y * BM;
    const int col0 = blockIdx.x * BN;
    const int z = blockIdx.z;
    const size_t kb0 = (size_t)z * CHUNK;
    const int NIT = (z == SPLITS - 1) ? (NVX - (SPLITS - 1) * CHUNK) / BK : CHUNK / BK;

    float acc[4][6][4];
#pragma unroll
    for (int a = 0; a < 4; a++)
#pragma unroll
        for (int b = 0; b < 6; b++)
#pragma unroll
            for (int c = 0; c < 4; c++) acc[a][b][c] = 0.0f;

    uint32_t a_u32[NSTAGE], b_u32[NSTAGE];
#pragma unroll
    for (int s = 0; s < NSTAGE; s++) {
        a_u32[s] = sm_b + (uint32_t)(s * STAGE_FLOATS) * 4u;
        b_u32[s] = a_u32[s] + (uint32_t)A_FLOATS * 4u;
    }

    // ldmatrix lane offsets
    const int arow = (lane & 7) + ((lane >> 3) & 1) * 8;
    const int acol = (lane >> 4) * 4;
    uint32_t offA[4];
#pragma unroll
    for (int mt = 0; mt < 4; mt++)
        offA[mt] = (uint32_t)(((wm * 64 + mt * 16 + arow) * SA + acol) * 4);

    const int brow = (lane & 7);
    const int bsel = (lane >> 4);
    const int bcol = ((lane >> 3) & 1) * 4;
    uint32_t offB[3];
#pragma unroll
    for (int p = 0; p < 3; p++)
        offB[p] = (uint32_t)(((wn * 48 + (2 * p + bsel) * 8 + brow) * SB + bcol) * 4);

    auto load_stage = [&](int s, size_t kb) {
        for (int idx = tid; idx < A_VEC; idx += NTHREADS) {
            int r = idx >> 3, o = idx & 7;
            cp_async16(a_u32[s] + (uint32_t)(r * SA + o * 4) * 4,
                       f + (size_t)(row0 + r) * NVX + kb + o * 4);
        }
#pragma unroll
        for (int p = 0; p < 3; p++) {
            int idx = tid + p * NTHREADS;
            int r = idx >> 3, o = idx & 7;
            cp_async16(b_u32[s] + (uint32_t)(r * SB + o * 4) * 4,
                       g_psiT + (size_t)(col0 + r) * NVX + kb + o * 4);
        }
        cp_commit();
    };

    // prologue: 3 stages in flight
    load_stage(0, kb0);
    load_stage(1, kb0 + BK);
    load_stage(2, kb0 + 2 * BK);

    for (int it = 0; it < NIT; ++it) {
        const int s = it & 3;
        if (it < NIT - 2) cp_wait2();
        else if (it == NIT - 2) cp_wait1();
        else cp_wait0();
        __syncthreads();   // stage s visible to all; stage (it-1)&3 reusable

        if (it + 3 < NIT)
            load_stage((s + 3) & 3, kb0 + (size_t)(it + 3) * BK);

        const uint32_t aS = a_u32[s];
        const uint32_t bS = b_u32[s];
#pragma unroll
        for (int kk = 0; kk < 4; kk++) {
            uint32_t afr[4][4];
#pragma unroll
            for (int mt = 0; mt < 4; mt++)
                ldsm_x4(afr[mt][0], afr[mt][1], afr[mt][2], afr[mt][3],
                        aS + offA[mt] + kk * 32);
            uint32_t bfr[6][2];
#pragma unroll
            for (int p = 0; p < 3; p++)
                ldsm_x4(bfr[2 * p][0], bfr[2 * p][1], bfr[2 * p + 1][0], bfr[2 * p + 1][1],
                        bS + offB[p] + kk * 32);
#pragma unroll
            for (int nt = 0; nt < 6; nt++)
#pragma unroll
                for (int mt = 0; mt < 4; mt++)
                    mma_tf32(acc[mt][nt], afr[mt], bfr[nt][0], bfr[nt][1]);
        }
    }

    // epilogue: atomic accumulate into g_w
#pragma unroll
    for (int mt = 0; mt < 4; mt++) {
        int r0 = row0 + wm * 64 + mt * 16 + q;
#pragma unroll
        for (int nt = 0; nt < 6; nt++) {
            int c0 = col0 + wn * 48 + nt * 8 + 2 * j;
            atomicAdd(&g_w[(size_t)r0 * KP + c0],           acc[mt][nt][0]);
            atomicAdd(&g_w[(size_t)r0 * KP + c0 + 1],       acc[mt][nt][1]);
            atomicAdd(&g_w[(size_t)(r0 + 8) * KP + c0],     acc[mt][nt][2]);
            atomicAdd(&g_w[(size_t)(r0 + 8) * KP + c0 + 1], acc[mt][nt][3]);
        }
    }
}

// ---------------- GEMM2 via mma.sync tf32: out = g_w (1024x288) @ phiT^T (288x2048) ----------
// CTA tile 64(M) x 256(N), BK=32, 9 K-iters. 256 threads: warps 2(M) x 4(N), warp tile 32x64.
// A (g_w) resident in smem, rna-rounded at staging. B (phiT) 3-stage cp.async.
#define G2M 64
#define G2N 256
#define G2_AST 292              // A smem row stride (288+4 floats): 4r bank pattern, 16B rows
#define G2_SB 36
#define G2_A_FLOATS (G2M * G2_AST)                 // 18688
#define G2_B_STAGE (G2N * G2_SB)                   // 9216
#define G2_SMEM_FLOATS (G2_A_FLOATS + 3 * G2_B_STAGE)   // 46336 floats = 185344 B

__global__ void __launch_bounds__(256, 1) gemm2_mma(float* __restrict__ out)
{
    extern __shared__ __align__(16) float sm[];
    uint32_t sm_b = smem_u32(sm);

    const int tid = threadIdx.x;
    const int lane = tid & 31;
    const int warp = tid >> 5;               // 0..7
    const int wm = warp & 1;                 // 0..1 (M)
    const int wn = warp >> 1;                // 0..3 (N)
    const int q = lane >> 2, j = lane & 3;

    const int row0 = blockIdx.y * G2M;
    const int col0 = blockIdx.x * G2N;

    uint32_t b_u32[3];
#pragma unroll
    for (int s = 0; s < 3; s++)
        b_u32[s] = sm_b + (uint32_t)(G2_A_FLOATS + s * G2_B_STAGE) * 4u;

    // ---- stage A (all 288 cols), rna-rounded ----
    for (int idx = tid; idx < G2M * 72; idx += 256) {
        int r = idx / 72, c = idx - (idx / 72) * 72;
        float4 v = *(const float4*)(g_w + (size_t)(row0 + r) * KP + c * 4);
        uint4 u;
        u.x = rna_tf32(v.x); u.y = rna_tf32(v.y); u.z = rna_tf32(v.z); u.w = rna_tf32(v.w);
        *(uint4*)(sm + r * G2_AST + c * 4) = u;
    }

    auto load_b = [&](int s, int k0) {
#pragma unroll
        for (int p = 0; p < 8; p++) {
            int idx = tid + p * 256;
            int r = idx >> 3, o = idx & 7;
            cp_async16(b_u32[s] + (uint32_t)(r * G2_SB + o * 4) * 4,
                       g_phiT + (size_t)(col0 + r) * KP + k0 + o * 4);
        }
        cp_commit();
    };
    load_b(0, 0);
    load_b(1, BK);

    // ldmatrix offsets
    const int arow = (lane & 7) + ((lane >> 3) & 1) * 8;
    const int acol = (lane >> 4) * 4;
    uint32_t offA[2];
#pragma unroll
    for (int mt = 0; mt < 2; mt++)
        offA[mt] = (uint32_t)(((wm * 32 + mt * 16 + arow) * G2_AST + acol) * 4);

    const int brow = (lane & 7);
    const int bsel = (lane >> 4);
    const int bcol = ((lane >> 3) & 1) * 4;
    uint32_t offB[4];
#pragma unroll
    for (int p = 0; p < 4; p++)
        offB[p] = (uint32_t)(((wn * 64 + (2 * p + bsel) * 8 + brow) * G2_SB + bcol) * 4);

    float acc[2][8][4];
#pragma unroll
    for (int a = 0; a < 2; a++)
#pragma unroll
        for (int b = 0; b < 8; b++)
#pragma unroll
            for (int c = 0; c < 4; c++) acc[a][b][c] = 0.0f;

    const int NIT2 = KP / BK;   // 9
    for (int it = 0; it < NIT2; ++it) {
        const int s = it % 3;
        if (it < NIT2 - 1) cp_wait1(); else cp_wait0();
        __syncthreads();

        if (it + 2 < NIT2) load_b((s + 2) % 3, (it + 2) * BK);

        const uint32_t bS = b_u32[s];
        const uint32_t kbase = (uint32_t)(it * BK) * 4u;
#pragma unroll
        for (int kk = 0; kk < 4; kk++) {
            uint32_t afr[2][4];
#pragma unroll
            for (int mt = 0; mt < 2; mt++)
                ldsm_x4(afr[mt][0], afr[mt][1], afr[mt][2], afr[mt][3],
                        sm_b + offA[mt] + kbase + kk * 32);
            uint32_t bfr[8][2];
#pragma unroll
            for (int p = 0; p < 4; p++)
                ldsm_x4(bfr[2 * p][0], bfr[2 * p][1], bfr[2 * p + 1][0], bfr[2 * p + 1][1],
                        bS + offB[p] + kk * 32);
#pragma unroll
            for (int nt = 0; nt < 8; nt++)
#pragma unroll
                for (int mt = 0; mt < 2; mt++)
                    mma_tf32(acc[mt][nt], afr[mt], bfr[nt][0], bfr[nt][1]);
        }
    }

    // direct store
#pragma unroll
    for (int mt = 0; mt < 2; mt++) {
        int r0 = row0 + wm * 32 + mt * 16 + q;
#pragma unroll
        for (int nt = 0; nt < 8; nt++) {
            int c0 = col0 + wn * 64 + nt * 8 + 2 * j;
            *(float2*)&out[(size_t)r0 * NXOUT + c0]       = make_float2(acc[mt][nt][0], acc[mt][nt][1]);
            *(float2*)&out[(size_t)(r0 + 8) * NXOUT + c0] = make_float2(acc[mt][nt][2], acc[mt][nt][3]);
        }
    }
}

extern "C" void kernel_launch(void* const* d_in, const int* in_sizes, int n_in,
                              void* d_out, int out_size)
{
    const float* x_out = (const float*)d_in[0];
    const float* f     = (const float*)d_in[1];
    const float* xs    = (const float*)d_in[2];
    const float* vs    = (const float*)d_in[3];
    const float* W1    = (const float*)d_in[4];
    const float* b1    = (const float*)d_in[5];
    const float* W2    = (const float*)d_in[6];
    const float* b2    = (const float*)d_in[7];
    const float* W3    = (const float*)d_in[8];
    const float* b3    = (const float*)d_in[9];
    float* out = (float*)d_out;

    static int smem_set = 0;
    if (!smem_set) {
        cudaFuncSetAttribute(gemm1_mma, cudaFuncAttributeMaxDynamicSharedMemorySize,
                             SMEM_FLOATS * 4);
        cudaFuncSetAttribute(gemm2_mma, cudaFuncAttributeMaxDynamicSharedMemorySize,
                             G2_SMEM_FLOATS * 4);
        smem_set = 1;
    }

    psi_kernel<<<NVX / 256, 256>>>(xs, vs, W1, b1, W2, b2, W3, b3);
    zero_misc_kernel<<<(ZERO_TOTAL + 255) / 256, 256>>>();
    phi_kernel<<<(NXOUT * KDIM + 255) / 256, 256>>>(x_out, xs);
    {
        dim3 grid(2, 4, SPLITS);   // N tiles, M tiles, split-K
        gemm1_mma<<<grid, NTHREADS, SMEM_FLOATS * 4>>>(f);
    }
    {
        dim3 grid(NXOUT / G2N, NT / G2M);
        gemm2_mma<<<grid, 256, G2_SMEM_FLOATS * 4>>>(out);
    }
}

// round 11
// speedup vs baseline: 1.7718x; 1.0245x over previous
#include <cuda_runtime.h>
#include <math.h>
#include <stdint.h>

#define NT 1024
#define NV 128
#define NXS 512
#define NVX 65536          // NV*NXS (contraction length of GEMM1)
#define KDIM 257
#define KP 288             // padded KDIM
#define NXOUT 2048

// -------- scratch (no allocations allowed) --------
__device__ float g_psiT[(size_t)KP * NVX];     // transposed psi * (hx*hv), tf32-rounded
__device__ float g_w[(size_t)NT * KP];         // weights accumulator
__device__ float g_phiT[(size_t)NXOUT * KP];   // fourier basis transposed [n][k], tf32-rounded

// ============================ helpers ============================
__device__ __forceinline__ uint32_t smem_u32(const void* p) {
    uint32_t a;
    asm("{ .reg .u64 t; cvta.to.shared.u64 t, %1; cvt.u32.u64 %0, t; }" : "=r"(a) : "l"(p));
    return a;
}
__device__ __forceinline__ uint32_t rna_tf32(float x) {
    uint32_t r;
    asm("cvt.rna.tf32.f32 %0, %1;" : "=r"(r) : "f"(x));
    return r;
}
__device__ __forceinline__ void mma_tf32(float* c, const uint32_t* a, uint32_t b0, uint32_t b1) {
    asm volatile(
        "mma.sync.aligned.m16n8k8.row.col.f32.tf32.tf32.f32 "
        "{%0,%1,%2,%3}, {%4,%5,%6,%7}, {%8,%9}, {%0,%1,%2,%3};"
        : "+f"(c[0]), "+f"(c[1]), "+f"(c[2]), "+f"(c[3])
        : "r"(a[0]), "r"(a[1]), "r"(a[2]), "r"(a[3]), "r"(b0), "r"(b1));
}
__device__ __forceinline__ void ldsm_x4(uint32_t& r0, uint32_t& r1, uint32_t& r2, uint32_t& r3,
                                        uint32_t a) {
    asm volatile("ldmatrix.sync.aligned.m8n8.x4.shared.b16 {%0,%1,%2,%3}, [%4];"
                 : "=r"(r0), "=r"(r1), "=r"(r2), "=r"(r3) : "r"(a));
}
__device__ __forceinline__ void cp_async16(uint32_t dst, const void* src) {
    asm volatile("cp.async.cg.shared.global [%0], [%1], 16;" :: "r"(dst), "l"(src) : "memory");
}
__device__ __forceinline__ void cp_commit() { asm volatile("cp.async.commit_group;" ::: "memory"); }
__device__ __forceinline__ void cp_wait0()  { asm volatile("cp.async.wait_group 0;" ::: "memory"); }
__device__ __forceinline__ void cp_wait1()  { asm volatile("cp.async.wait_group 1;" ::: "memory"); }

// ---------------- Psi MLP: (x,v) -> 257 (+ zero pad to 288), transposed + scaled ----------------
__global__ void psi_kernel(const float* __restrict__ xs, const float* __restrict__ vs,
                           const float* __restrict__ W1, const float* __restrict__ b1,
                           const float* __restrict__ W2, const float* __restrict__ b2,
                           const float* __restrict__ W3, const float* __restrict__ b3)
{
    __shared__ float sW1[128];
    __shared__ float sb1[64];
    __shared__ float sW2[64 * 32];
    __shared__ float sb2[32];
    __shared__ float sW3[32 * KDIM];
    __shared__ float sb3[KDIM];

    int tid = threadIdx.x;
    for (int i = tid; i < 128; i += 256)       sW1[i] = W1[i];
    for (int i = tid; i < 64; i += 256)        sb1[i] = b1[i];
    for (int i = tid; i < 64 * 32; i += 256)   sW2[i] = W2[i];
    if (tid < 32)                              sb2[tid] = b2[tid];
    for (int i = tid; i < 32 * KDIM; i += 256) sW3[i] = W3[i];
    for (int i = tid; i < KDIM; i += 256)      sb3[i] = b3[i];
    __syncthreads();

    int p = blockIdx.x * 256 + tid;
    int v = p >> 9;
    int x = p & 511;
    float xin = xs[x];
    float vin = vs[v];
    float scale = (xs[1] - xs[0]) * (vs[1] - vs[0]);   // hx * hv

    float h1[64];
#pragma unroll
    for (int j = 0; j < 64; j++) {
        float s = fmaf(xin, sW1[j], fmaf(vin, sW1[64 + j], sb1[j]));
        h1[j] = fmaxf(s, 0.0f);
    }
    float h2[32];
#pragma unroll
    for (int j = 0; j < 32; j++) {
        float s = sb2[j];
#pragma unroll
        for (int i = 0; i < 64; i++) s = fmaf(h1[i], sW2[i * 32 + j], s);
        h2[j] = fmaxf(s, 0.0f);
    }
#pragma unroll 2
    for (int k = 0; k < KDIM; k++) {
        float s = sb3[k];
#pragma unroll
        for (int j = 0; j < 32; j++) s = fmaf(h2[j], sW3[j * KDIM + k], s);
        g_psiT[(size_t)k * NVX + p] = __uint_as_float(rna_tf32(s * scale));
    }
    // zero padding rows [KDIM, KP)
#pragma unroll
    for (int k = KDIM; k < KP; k++)
        g_psiT[(size_t)k * NVX + p] = 0.0f;
}

// ---------------- zero g_w ----------------
__global__ void zero_w_kernel()
{
    int i = blockIdx.x * 256 + threadIdx.x;
    if (i < NT * KP) g_w[i] = 0.0f;
}

// ---------------- phi table transposed: [Nx_out][KP], tf32-rounded, pad zeros ----------------
__global__ void phi_kernel(const float* __restrict__ x_out, const float* __restrict__ xs)
{
    int idx = blockIdx.x * 256 + threadIdx.x;
    if (idx >= NXOUT * KP) return;
    int n = idx / KP;
    int k = idx - n * KP;
    float val = 0.0f;
    if (k < KDIM) {
        float w = (2.0f * 3.14159265358979323846f) / (xs[NXS - 1] - xs[0]);
        float xo = x_out[n];
        if (k < 128) val = sinf((float)(k + 1) * w * xo);
        else         val = cosf((float)(k - 128) * w * xo);
        val = __uint_as_float(rna_tf32(val));
    }
    g_phiT[idx] = val;
}

// ---------------- GEMM1: mma.sync tf32, 2 CTAs/SM, 2-stage cp.async, ldmatrix ----------------
// C (1024 x 288) += f (1024 x 65536) @ psiT^T
// CTA tile 128x144, BK=32, 192 threads: warps 2(M) x 3(N), warp tile 64x48.
// Split-K: 18 uneven chunks (17 x 3648 + 1 x 3520), grid 2 x 8 x 18 = 288 CTAs = 2/SM.
#define BM 128
#define BN 144
#define BK 32
#define NTHREADS 192
#define SPLITS 18
#define CHUNK 3648              // 114 * 32 ; last chunk = 3520 = 110 * 32
#define SA 36                   // bank = (4*row + j) % 32 -> conflict-free; 144B rows
#define SB 36
#define A_FLOATS (BM * SA)      // 4608
#define B_FLOATS (BN * SB)      // 5184
#define STAGE_FLOATS (A_FLOATS + B_FLOATS)          // 9792
#define NSTAGE 2
#define SMEM_FLOATS (NSTAGE * STAGE_FLOATS)         // 19584 floats = 78336 B
#define A_VEC (BM * 8)          // 1024 float4 per A tile
#define B_VEC (BN * 8)          // 1152 float4 per B tile

__global__ void __launch_bounds__(NTHREADS, 2) gemm1_mma(const float* __restrict__ f)
{
    extern __shared__ __align__(16) float sm[];
    uint32_t sm_b = smem_u32(sm);

    const int tid = threadIdx.x;
    const int lane = tid & 31;
    const int warp = tid >> 5;               // 0..5
    const int wm = warp & 1;                 // 0..1 (M)
    const int wn = warp >> 1;                // 0..2 (N)
    const int q = lane >> 2, j = lane & 3;

    const int row0 = blockIdx.y * BM;
    const int col0 = blockIdx.x * BN;
    const int z = blockIdx.z;
    const size_t kb0 = (size_t)z * CHUNK;
    const int NIT = (z == SPLITS - 1) ? (NVX - (SPLITS - 1) * CHUNK) / BK : CHUNK / BK;

    float acc[4][6][4];
#pragma unroll
    for (int a = 0; a < 4; a++)
#pragma unroll
        for (int b = 0; b < 6; b++)
#pragma unroll
            for (int c = 0; c < 4; c++) acc[a][b][c] = 0.0f;

    uint32_t a_u32[NSTAGE], b_u32[NSTAGE];
#pragma unroll
    for (int s = 0; s < NSTAGE; s++) {
        a_u32[s] = sm_b + (uint32_t)(s * STAGE_FLOATS) * 4u;
        b_u32[s] = a_u32[s] + (uint32_t)A_FLOATS * 4u;
    }

    // ldmatrix lane offsets
    const int arow = (lane & 7) + ((lane >> 3) & 1) * 8;
    const int acol = (lane >> 4) * 4;
    uint32_t offA[4];
#pragma unroll
    for (int mt = 0; mt < 4; mt++)
        offA[mt] = (uint32_t)(((wm * 64 + mt * 16 + arow) * SA + acol) * 4);

    const int brow = (lane & 7);
    const int bsel = (lane >> 4);
    const int bcol = ((lane >> 3) & 1) * 4;
    uint32_t offB[3];
#pragma unroll
    for (int p = 0; p < 3; p++)
        offB[p] = (uint32_t)(((wn * 48 + (2 * p + bsel) * 8 + brow) * SB + bcol) * 4);

    auto load_stage = [&](int s, size_t kb) {
        // A: 1024 float4 over 192 threads
        for (int idx = tid; idx < A_VEC; idx += NTHREADS) {
            int r = idx >> 3, o = idx & 7;
            cp_async16(a_u32[s] + (uint32_t)(r * SA + o * 4) * 4,
                       f + (size_t)(row0 + r) * NVX + kb + o * 4);
        }
        // B: 1152 float4 = 6 per thread exactly
#pragma unroll
        for (int p = 0; p < 6; p++) {
            int idx = tid + p * NTHREADS;
            int r = idx >> 3, o = idx & 7;
            cp_async16(b_u32[s] + (uint32_t)(r * SB + o * 4) * 4,
                       g_psiT + (size_t)(col0 + r) * NVX + kb + o * 4);
        }
        cp_commit();
    };

    // prologue: both stages in flight
    load_stage(0, kb0);
    load_stage(1, kb0 + BK);

    for (int it = 0; it < NIT; ++it) {
        const int s = it & 1;
        if (it + 1 < NIT) cp_wait1(); else cp_wait0();
        __syncthreads();

        const uint32_t aS = a_u32[s];
        const uint32_t bS = b_u32[s];
#pragma unroll
        for (int kk = 0; kk < 4; kk++) {
            uint32_t afr[4][4];
#pragma unroll
            for (int mt = 0; mt < 4; mt++)
                ldsm_x4(afr[mt][0], afr[mt][1], afr[mt][2], afr[mt][3],
                        aS + offA[mt] + kk * 32);
            uint32_t bfr[6][2];
#pragma unroll
            for (int p = 0; p < 3; p++)
                ldsm_x4(bfr[2 * p][0], bfr[2 * p][1], bfr[2 * p + 1][0], bfr[2 * p + 1][1],
                        bS + offB[p] + kk * 32);
#pragma unroll
            for (int nt = 0; nt < 6; nt++)
#pragma unroll
                for (int mt = 0; mt < 4; mt++)
                    mma_tf32(acc[mt][nt], afr[mt], bfr[nt][0], bfr[nt][1]);
        }
        __syncthreads();
        if (it + 2 < NIT)
            load_stage(s, kb0 + (size_t)(it + 2) * BK);
    }

    // epilogue: atomic accumulate into g_w
#pragma unroll
    for (int mt = 0; mt < 4; mt++) {
        int r0 = row0 + wm * 64 + mt * 16 + q;
#pragma unroll
        for (int nt = 0; nt < 6; nt++) {
            int c0 = col0 + wn * 48 + nt * 8 + 2 * j;
            atomicAdd(&g_w[(size_t)r0 * KP + c0],           acc[mt][nt][0]);
            atomicAdd(&g_w[(size_t)r0 * KP + c0 + 1],       acc[mt][nt][1]);
            atomicAdd(&g_w[(size_t)(r0 + 8) * KP + c0],     acc[mt][nt][2]);
            atomicAdd(&g_w[(size_t)(r0 + 8) * KP + c0 + 1], acc[mt][nt][3]);
        }
    }
}

// ---------------- GEMM2 via mma.sync tf32: out = g_w (1024x288) @ phiT^T (288x2048) ----------
// CTA tile 64(M) x 256(N), BK=32, 9 K-iters. 256 threads: warps 2(M) x 4(N), warp tile 32x64.
#define G2M 64
#define G2N 256
#define G2_AST 292
#define G2_SB 36
#define G2_A_FLOATS (G2M * G2_AST)                 // 18688
#define G2_B_STAGE (G2N * G2_SB)                   // 9216
#define G2_SMEM_FLOATS (G2_A_FLOATS + 3 * G2_B_STAGE)   // 46336 floats = 185344 B

__global__ void __launch_bounds__(256, 1) gemm2_mma(float* __restrict__ out)
{
    extern __shared__ __align__(16) float sm[];
    uint32_t sm_b = smem_u32(sm);

    const int tid = threadIdx.x;
    const int lane = tid & 31;
    const int warp = tid >> 5;
    const int wm = warp & 1;
    const int wn = warp >> 1;
    const int q = lane >> 2, j = lane & 3;

    const int row0 = blockIdx.y * G2M;
    const int col0 = blockIdx.x * G2N;

    uint32_t b_u32[3];
#pragma unroll
    for (int s = 0; s < 3; s++)
        b_u32[s] = sm_b + (uint32_t)(G2_A_FLOATS + s * G2_B_STAGE) * 4u;

    for (int idx = tid; idx < G2M * 72; idx += 256) {
        int r = idx / 72, c = idx - (idx / 72) * 72;
        float4 v = *(const float4*)(g_w + (size_t)(row0 + r) * KP + c * 4);
        uint4 u;
        u.x = rna_tf32(v.x); u.y = rna_tf32(v.y); u.z = rna_tf32(v.z); u.w = rna_tf32(v.w);
        *(uint4*)(sm + r * G2_AST + c * 4) = u;
    }

    auto load_b = [&](int s, int k0) {
#pragma unroll
        for (int p = 0; p < 8; p++) {
            int idx = tid + p * 256;
            int r = idx >> 3, o = idx & 7;
            cp_async16(b_u32[s] + (uint32_t)(r * G2_SB + o * 4) * 4,
                       g_phiT + (size_t)(col0 + r) * KP + k0 + o * 4);
        }
        cp_commit();
    };
    load_b(0, 0);
    load_b(1, BK);

    const int arow = (lane & 7) + ((lane >> 3) & 1) * 8;
    const int acol = (lane >> 4) * 4;
    uint32_t offA[2];
#pragma unroll
    for (int mt = 0; mt < 2; mt++)
        offA[mt] = (uint32_t)(((wm * 32 + mt * 16 + arow) * G2_AST + acol) * 4);

    const int brow = (lane & 7);
    const int bsel = (lane >> 4);
    const int bcol = ((lane >> 3) & 1) * 4;
    uint32_t offB[4];
#pragma unroll
    for (int p = 0; p < 4; p++)
        offB[p] = (uint32_t)(((wn * 64 + (2 * p + bsel) * 8 + brow) * G2_SB + bcol) * 4);

    float acc[2][8][4];
#pragma unroll
    for (int a = 0; a < 2; a++)
#pragma unroll
        for (int b = 0; b < 8; b++)
#pragma unroll
            for (int c = 0; c < 4; c++) acc[a][b][c] = 0.0f;

    const int NIT2 = KP / BK;   // 9
    for (int it = 0; it < NIT2; ++it) {
        const int s = it % 3;
        if (it < NIT2 - 1) cp_wait1(); else cp_wait0();
        __syncthreads();

        if (it + 2 < NIT2) load_b((s + 2) % 3, (it + 2) * BK);

        const uint32_t bS = b_u32[s];
        const uint32_t kbase = (uint32_t)(it * BK) * 4u;
#pragma unroll
        for (int kk = 0; kk < 4; kk++) {
            uint32_t afr[2][4];
#pragma unroll
            for (int mt = 0; mt < 2; mt++)
                ldsm_x4(afr[mt][0], afr[mt][1], afr[mt][2], afr[mt][3],
                        sm_b + offA[mt] + kbase + kk * 32);
            uint32_t bfr[8][2];
#pragma unroll
            for (int p = 0; p < 4; p++)
                ldsm_x4(bfr[2 * p][0], bfr[2 * p][1], bfr[2 * p + 1][0], bfr[2 * p + 1][1],
                        bS + offB[p] + kk * 32);
#pragma unroll
            for (int nt = 0; nt < 8; nt++)
#pragma unroll
                for (int mt = 0; mt < 2; mt++)
                    mma_tf32(acc[mt][nt], afr[mt], bfr[nt][0], bfr[nt][1]);
        }
    }

#pragma unroll
    for (int mt = 0; mt < 2; mt++) {
        int r0 = row0 + wm * 32 + mt * 16 + q;
#pragma unroll
        for (int nt = 0; nt < 8; nt++) {
            int c0 = col0 + wn * 64 + nt * 8 + 2 * j;
            *(float2*)&out[(size_t)r0 * NXOUT + c0]       = make_float2(acc[mt][nt][0], acc[mt][nt][1]);
            *(float2*)&out[(size_t)(r0 + 8) * NXOUT + c0] = make_float2(acc[mt][nt][2], acc[mt][nt][3]);
        }
    }
}

extern "C" void kernel_launch(void* const* d_in, const int* in_sizes, int n_in,
                              void* d_out, int out_size)
{
    const float* x_out = (const float*)d_in[0];
    const float* f     = (const float*)d_in[1];
    const float* xs    = (const float*)d_in[2];
    const float* vs    = (const float*)d_in[3];
    const float* W1    = (const float*)d_in[4];
    const float* b1    = (const float*)d_in[5];
    const float* W2    = (const float*)d_in[6];
    const float* b2    = (const float*)d_in[7];
    const float* W3    = (const float*)d_in[8];
    const float* b3    = (const float*)d_in[9];
    float* out = (float*)d_out;

    static int smem_set = 0;
    if (!smem_set) {
        cudaFuncSetAttribute(gemm1_mma, cudaFuncAttributeMaxDynamicSharedMemorySize,
                             SMEM_FLOATS * 4);
        cudaFuncSetAttribute(gemm2_mma, cudaFuncAttributeMaxDynamicSharedMemorySize,
                             G2_SMEM_FLOATS * 4);
        smem_set = 1;
    }

    psi_kernel<<<NVX / 256, 256>>>(xs, vs, W1, b1, W2, b2, W3, b3);
    zero_w_kernel<<<(NT * KP + 255) / 256, 256>>>();
    phi_kernel<<<(NXOUT * KP + 255) / 256, 256>>>(x_out, xs);
    {
        dim3 grid(2, 8, SPLITS);   // N tiles, M tiles, split-K
        gemm1_mma<<<grid, NTHREADS, SMEM_FLOATS * 4>>>(f);
    }
    {
        dim3 grid(NXOUT / G2N, NT / G2M);
        gemm2_mma<<<grid, 256, G2_SMEM_FLOATS * 4>>>(out);
    }
}

// round 12
// speedup vs baseline: 5.7413x; 3.2404x over previous
#include <cuda_runtime.h>
#include <math.h>
#include <stdint.h>

#define NT 1024
#define NV 128
#define NXS 512
#define NVX 65536          // NV*NXS (contraction length of GEMM1)
#define KDIM 257
#define KP 288             // padded KDIM
#define NXOUT 2048
#define NH 48              // padded hidden+1 (33 -> 48)

// -------- scratch (no allocations allowed) --------
__device__ float g_h2T[(size_t)NH * NVX];      // [j][p]: relu layer-2 (j<32), ones (j=32), 0 pad
__device__ float g_w2[(size_t)NT * NH];        // f @ [H2|1]  (1024 x 48)
__device__ float g_w[(size_t)NT * KP];         // weights (1024 x 288)
__device__ float g_phiT[(size_t)NXOUT * KP];   // fourier basis transposed [n][k], tf32-rounded

// ============================ helpers ============================
__device__ __forceinline__ uint32_t smem_u32(const void* p) {
    uint32_t a;
    asm("{ .reg .u64 t; cvta.to.shared.u64 t, %1; cvt.u32.u64 %0, t; }" : "=r"(a) : "l"(p));
    return a;
}
__device__ __forceinline__ uint32_t rna_tf32(float x) {
    uint32_t r;
    asm("cvt.rna.tf32.f32 %0, %1;" : "=r"(r) : "f"(x));
    return r;
}
__device__ __forceinline__ void mma_tf32(float* c, const uint32_t* a, uint32_t b0, uint32_t b1) {
    asm volatile(
        "mma.sync.aligned.m16n8k8.row.col.f32.tf32.tf32.f32 "
        "{%0,%1,%2,%3}, {%4,%5,%6,%7}, {%8,%9}, {%0,%1,%2,%3};"
        : "+f"(c[0]), "+f"(c[1]), "+f"(c[2]), "+f"(c[3])
        : "r"(a[0]), "r"(a[1]), "r"(a[2]), "r"(a[3]), "r"(b0), "r"(b1));
}
__device__ __forceinline__ void ldsm_x4(uint32_t& r0, uint32_t& r1, uint32_t& r2, uint32_t& r3,
                                        uint32_t a) {
    asm volatile("ldmatrix.sync.aligned.m8n8.x4.shared.b16 {%0,%1,%2,%3}, [%4];"
                 : "=r"(r0), "=r"(r1), "=r"(r2), "=r"(r3) : "r"(a));
}
__device__ __forceinline__ void cp_async16(uint32_t dst, const void* src) {
    asm volatile("cp.async.cg.shared.global [%0], [%1], 16;" :: "r"(dst), "l"(src) : "memory");
}
__device__ __forceinline__ void cp_commit() { asm volatile("cp.async.commit_group;" ::: "memory"); }
__device__ __forceinline__ void cp_wait0()  { asm volatile("cp.async.wait_group 0;" ::: "memory"); }
__device__ __forceinline__ void cp_wait1()  { asm volatile("cp.async.wait_group 1;" ::: "memory"); }

// ---------------- Psi MLP layers 1-2 only: h2 (32) + ones column, transposed ----------------
__global__ void psi2_kernel(const float* __restrict__ xs, const float* __restrict__ vs,
                            const float* __restrict__ W1, const float* __restrict__ b1,
                            const float* __restrict__ W2, const float* __restrict__ b2)
{
    __shared__ float sW1[128];
    __shared__ float sb1[64];
    __shared__ float sW2[64 * 32];
    __shared__ float sb2[32];

    int tid = threadIdx.x;
    for (int i = tid; i < 128; i += 256)      sW1[i] = W1[i];
    for (int i = tid; i < 64; i += 256)       sb1[i] = b1[i];
    for (int i = tid; i < 64 * 32; i += 256)  sW2[i] = W2[i];
    if (tid < 32)                             sb2[tid] = b2[tid];
    __syncthreads();

    int p = blockIdx.x * 256 + tid;
    int v = p >> 9;
    int x = p & 511;
    float xin = xs[x];
    float vin = vs[v];

    float h1[64];
#pragma unroll
    for (int j = 0; j < 64; j++) {
        float s = fmaf(xin, sW1[j], fmaf(vin, sW1[64 + j], sb1[j]));
        h1[j] = fmaxf(s, 0.0f);
    }
#pragma unroll
    for (int j = 0; j < 32; j++) {
        float s = sb2[j];
#pragma unroll
        for (int i = 0; i < 64; i++) s = fmaf(h1[i], sW2[i * 32 + j], s);
        g_h2T[(size_t)j * NVX + p] = __uint_as_float(rna_tf32(fmaxf(s, 0.0f)));
    }
    g_h2T[(size_t)32 * NVX + p] = 1.0f;
#pragma unroll
    for (int j = 33; j < NH; j++)
        g_h2T[(size_t)j * NVX + p] = 0.0f;
}

// ---------------- zero g_w2 ----------------
__global__ void zero_w2_kernel()
{
    int i = blockIdx.x * 256 + threadIdx.x;
    if (i < NT * NH) g_w2[i] = 0.0f;
}

// ---------------- phi table transposed: [Nx_out][KP], tf32-rounded, pad zeros ----------------
__global__ void phi_kernel(const float* __restrict__ x_out, const float* __restrict__ xs)
{
    int idx = blockIdx.x * 256 + threadIdx.x;
    if (idx >= NXOUT * KP) return;
    int n = idx / KP;
    int k = idx - n * KP;
    float val = 0.0f;
    if (k < KDIM) {
        float w = (2.0f * 3.14159265358979323846f) / (xs[NXS - 1] - xs[0]);
        float xo = x_out[n];
        if (k < 128) val = sinf((float)(k + 1) * w * xo);
        else         val = cosf((float)(k - 128) * w * xo);
        val = __uint_as_float(rna_tf32(val));
    }
    g_phiT[idx] = val;
}

// ---------------- GEMM1b: g_w2 (1024x48) += f (1024x65536) @ h2T^T ----------------
// CTA tile 128x48, BK=64, 192 threads: warps 2(M) x 3(N), warp tile 64x16.
// Split-K 36 (16 x 29 iters + 20 x 28 iters of BK=64), grid (1, 8, 36) = 288 CTAs, 2/SM.
#define B1_BM 128
#define B1_BN 48
#define B1_BK 64
#define B1_THREADS 192
#define B1_SPLITS 36
#define B1_SA 68                 // bank pattern (4r+j)%32 -> conflict-free ldmatrix
#define B1_A_FLOATS (B1_BM * B1_SA)     // 8704
#define B1_B_FLOATS (B1_BN * B1_SA)     // 3264
#define B1_STAGE (B1_A_FLOATS + B1_B_FLOATS)   // 11968
#define B1_SMEM_FLOATS (2 * B1_STAGE)          // 23936 floats = 95744 B

__global__ void __launch_bounds__(B1_THREADS, 2) gemm1b(const float* __restrict__ f)
{
    extern __shared__ __align__(16) float sm[];
    uint32_t sm_b = smem_u32(sm);

    const int tid = threadIdx.x;
    const int lane = tid & 31;
    const int warp = tid >> 5;               // 0..5
    const int wm = warp & 1;                 // 0..1 (M)
    const int wn = warp >> 1;                // 0..2 (N)
    const int q = lane >> 2, j = lane & 3;

    const int row0 = blockIdx.y * B1_BM;
    const int z = blockIdx.z;
    int it0, nit;
    if (z < 16) { it0 = z * 29;               nit = 29; }
    else        { it0 = 16 * 29 + (z - 16) * 28; nit = 28; }
    const size_t kb0 = (size_t)it0 * B1_BK;

    float acc[4][2][4];
#pragma unroll
    for (int a = 0; a < 4; a++)
#pragma unroll
        for (int b = 0; b < 2; b++)
#pragma unroll
            for (int c = 0; c < 4; c++) acc[a][b][c] = 0.0f;

    uint32_t a_u32[2], b_u32[2];
#pragma unroll
    for (int s = 0; s < 2; s++) {
        a_u32[s] = sm_b + (uint32_t)(s * B1_STAGE) * 4u;
        b_u32[s] = a_u32[s] + (uint32_t)B1_A_FLOATS * 4u;
    }

    // ldmatrix lane offsets
    const int arow = (lane & 7) + ((lane >> 3) & 1) * 8;
    const int acol = (lane >> 4) * 4;
    uint32_t offA[4];
#pragma unroll
    for (int mt = 0; mt < 4; mt++)
        offA[mt] = (uint32_t)(((wm * 64 + mt * 16 + arow) * B1_SA + acol) * 4);

    const int brow = (lane & 7);
    const int bsel = (lane >> 4);
    const int bcol = ((lane >> 3) & 1) * 4;
    const uint32_t offB = (uint32_t)(((wn * 16 + bsel * 8 + brow) * B1_SA + bcol) * 4);

    auto load_stage = [&](int s, size_t kb) {
        // A: 128 rows x 16 float4 = 2048 over 192 threads
        for (int idx = tid; idx < B1_BM * 16; idx += B1_THREADS) {
            int r = idx >> 4, o = idx & 15;
            cp_async16(a_u32[s] + (uint32_t)(r * B1_SA + o * 4) * 4,
                       f + (size_t)(row0 + r) * NVX + kb + o * 4);
        }
        // B: 48 rows x 16 float4 = 768 = 4/thread
#pragma unroll
        for (int p = 0; p < 4; p++) {
            int idx = tid + p * B1_THREADS;
            int r = idx >> 4, o = idx & 15;
            cp_async16(b_u32[s] + (uint32_t)(r * B1_SA + o * 4) * 4,
                       g_h2T + (size_t)r * NVX + kb + o * 4);
        }
        cp_commit();
    };

    load_stage(0, kb0);
    load_stage(1, kb0 + B1_BK);

    for (int it = 0; it < nit; ++it) {
        const int s = it & 1;
        if (it + 1 < nit) cp_wait1(); else cp_wait0();
        __syncthreads();

        const uint32_t aS = a_u32[s];
        const uint32_t bS = b_u32[s];
#pragma unroll
        for (int kk = 0; kk < 8; kk++) {
            uint32_t afr[4][4];
#pragma unroll
            for (int mt = 0; mt < 4; mt++)
                ldsm_x4(afr[mt][0], afr[mt][1], afr[mt][2], afr[mt][3],
                        aS + offA[mt] + kk * 32);
            uint32_t bfr[2][2];
            ldsm_x4(bfr[0][0], bfr[0][1], bfr[1][0], bfr[1][1], bS + offB + kk * 32);
#pragma unroll
            for (int nt = 0; nt < 2; nt++)
#pragma unroll
                for (int mt = 0; mt < 4; mt++)
                    mma_tf32(acc[mt][nt], afr[mt], bfr[nt][0], bfr[nt][1]);
        }
        __syncthreads();
        if (it + 2 < nit)
            load_stage(s, kb0 + (size_t)(it + 2) * B1_BK);
    }

    // atomic accumulate into g_w2
#pragma unroll
    for (int mt = 0; mt < 4; mt++) {
        int r0 = row0 + wm * 64 + mt * 16 + q;
#pragma unroll
        for (int nt = 0; nt < 2; nt++) {
            int c0 = wn * 16 + nt * 8 + 2 * j;
            atomicAdd(&g_w2[r0 * NH + c0],           acc[mt][nt][0]);
            atomicAdd(&g_w2[r0 * NH + c0 + 1],       acc[mt][nt][1]);
            atomicAdd(&g_w2[(r0 + 8) * NH + c0],     acc[mt][nt][2]);
            atomicAdd(&g_w2[(r0 + 8) * NH + c0 + 1], acc[mt][nt][3]);
        }
    }
}

// ---------------- small gemm: g_w (1024x288, pad zeros) = scale * g_w2 @ [W3; b3] ----------------
__global__ void small_gemm(const float* __restrict__ xs, const float* __restrict__ vs,
                           const float* __restrict__ W3, const float* __restrict__ b3)
{
    __shared__ float sa[33];
    int t = blockIdx.x;
    int tid = threadIdx.x;
    if (tid < 33) sa[tid] = g_w2[t * NH + tid];
    __syncthreads();
    float scale = (xs[1] - xs[0]) * (vs[1] - vs[0]);   // hx * hv
    for (int k = tid; k < KP; k += 256) {
        float s = 0.0f;
        if (k < KDIM) {
            s = sa[32] * b3[k];
#pragma unroll
            for (int jj = 0; jj < 32; jj++) s = fmaf(sa[jj], W3[jj * KDIM + k], s);
            s *= scale;
        }
        g_w[(size_t)t * KP + k] = s;
    }
}

// ---------------- GEMM2 via mma.sync tf32: out = g_w (1024x288) @ phiT^T (288x2048) ----------
#define BK 32
#define G2M 64
#define G2N 256
#define G2_AST 292
#define G2_SB 36
#define G2_A_FLOATS (G2M * G2_AST)                 // 18688
#define G2_B_STAGE (G2N * G2_SB)                   // 9216
#define G2_SMEM_FLOATS (G2_A_FLOATS + 3 * G2_B_STAGE)   // 46336 floats = 185344 B

__global__ void __launch_bounds__(256, 1) gemm2_mma(float* __restrict__ out)
{
    extern __shared__ __align__(16) float sm[];
    uint32_t sm_b = smem_u32(sm);

    const int tid = threadIdx.x;
    const int lane = tid & 31;
    const int warp = tid >> 5;
    const int wm = warp & 1;
    const int wn = warp >> 1;
    const int q = lane >> 2, j = lane & 3;

    const int row0 = blockIdx.y * G2M;
    const int col0 = blockIdx.x * G2N;

    uint32_t b_u32[3];
#pragma unroll
    for (int s = 0; s < 3; s++)
        b_u32[s] = sm_b + (uint32_t)(G2_A_FLOATS + s * G2_B_STAGE) * 4u;

    for (int idx = tid; idx < G2M * 72; idx += 256) {
        int r = idx / 72, c = idx - (idx / 72) * 72;
        float4 v = *(const float4*)(g_w + (size_t)(row0 + r) * KP + c * 4);
        uint4 u;
        u.x = rna_tf32(v.x); u.y = rna_tf32(v.y); u.z = rna_tf32(v.z); u.w = rna_tf32(v.w);
        *(uint4*)(sm + r * G2_AST + c * 4) = u;
    }

    auto load_b = [&](int s, int k0) {
#pragma unroll
        for (int p = 0; p < 8; p++) {
            int idx = tid + p * 256;
            int r = idx >> 3, o = idx & 7;
            cp_async16(b_u32[s] + (uint32_t)(r * G2_SB + o * 4) * 4,
                       g_phiT + (size_t)(col0 + r) * KP + k0 + o * 4);
        }
        cp_commit();
    };
    load_b(0, 0);
    load_b(1, BK);

    const int arow = (lane & 7) + ((lane >> 3) & 1) * 8;
    const int acol = (lane >> 4) * 4;
    uint32_t offA[2];
#pragma unroll
    for (int mt = 0; mt < 2; mt++)
        offA[mt] = (uint32_t)(((wm * 32 + mt * 16 + arow) * G2_AST + acol) * 4);

    const int brow = (lane & 7);
    const int bsel = (lane >> 4);
    const int bcol = ((lane >> 3) & 1) * 4;
    uint32_t offB[4];
#pragma unroll
    for (int p = 0; p < 4; p++)
        offB[p] = (uint32_t)(((wn * 64 + (2 * p + bsel) * 8 + brow) * G2_SB + bcol) * 4);

    float acc[2][8][4];
#pragma unroll
    for (int a = 0; a < 2; a++)
#pragma unroll
        for (int b = 0; b < 8; b++)
#pragma unroll
            for (int c = 0; c < 4; c++) acc[a][b][c] = 0.0f;

    const int NIT2 = KP / BK;   // 9
    for (int it = 0; it < NIT2; ++it) {
        const int s = it % 3;
        if (it < NIT2 - 1) cp_wait1(); else cp_wait0();
        __syncthreads();

        if (it + 2 < NIT2) load_b((s + 2) % 3, (it + 2) * BK);

        const uint32_t bS = b_u32[s];
        const uint32_t kbase = (uint32_t)(it * BK) * 4u;
#pragma unroll
        for (int kk = 0; kk < 4; kk++) {
            uint32_t afr[2][4];
#pragma unroll
            for (int mt = 0; mt < 2; mt++)
                ldsm_x4(afr[mt][0], afr[mt][1], afr[mt][2], afr[mt][3],
                        sm_b + offA[mt] + kbase + kk * 32);
            uint32_t bfr[8][2];
#pragma unroll
            for (int p = 0; p < 4; p++)
                ldsm_x4(bfr[2 * p][0], bfr[2 * p][1], bfr[2 * p + 1][0], bfr[2 * p + 1][1],
                        bS + offB[p] + kk * 32);
#pragma unroll
            for (int nt = 0; nt < 8; nt++)
#pragma unroll
                for (int mt = 0; mt < 2; mt++)
                    mma_tf32(acc[mt][nt], afr[mt], bfr[nt][0], bfr[nt][1]);
        }
    }

#pragma unroll
    for (int mt = 0; mt < 2; mt++) {
        int r0 = row0 + wm * 32 + mt * 16 + q;
#pragma unroll
        for (int nt = 0; nt < 8; nt++) {
            int c0 = col0 + wn * 64 + nt * 8 + 2 * j;
            *(float2*)&out[(size_t)r0 * NXOUT + c0]       = make_float2(acc[mt][nt][0], acc[mt][nt][1]);
            *(float2*)&out[(size_t)(r0 + 8) * NXOUT + c0] = make_float2(acc[mt][nt][2], acc[mt][nt][3]);
        }
    }
}

extern "C" void kernel_launch(void* const* d_in, const int* in_sizes, int n_in,
                              void* d_out, int out_size)
{
    const float* x_out = (const float*)d_in[0];
    const float* f     = (const float*)d_in[1];
    const float* xs    = (const float*)d_in[2];
    const float* vs    = (const float*)d_in[3];
    const float* W1    = (const float*)d_in[4];
    const float* b1    = (const float*)d_in[5];
    const float* W2    = (const float*)d_in[6];
    const float* b2    = (const float*)d_in[7];
    const float* W3    = (const float*)d_in[8];
    const float* b3    = (const float*)d_in[9];
    float* out = (float*)d_out;

    static int smem_set = 0;
    if (!smem_set) {
        cudaFuncSetAttribute(gemm1b, cudaFuncAttributeMaxDynamicSharedMemorySize,
                             B1_SMEM_FLOATS * 4);
        cudaFuncSetAttribute(gemm2_mma, cudaFuncAttributeMaxDynamicSharedMemorySize,
                             G2_SMEM_FLOATS * 4);
        smem_set = 1;
    }

    psi2_kernel<<<NVX / 256, 256>>>(xs, vs, W1, b1, W2, b2);
    zero_w2_kernel<<<(NT * NH + 255) / 256, 256>>>();
    phi_kernel<<<(NXOUT * KP + 255) / 256, 256>>>(x_out, xs);
    {
        dim3 grid(1, NT / B1_BM, B1_SPLITS);   // 1 x 8 x 36 = 288 CTAs
        gemm1b<<<grid, B1_THREADS, B1_SMEM_FLOATS * 4>>>(f);
    }
    small_gemm<<<NT, 256>>>(xs, vs, W3, b3);
    {
        dim3 grid(NXOUT / G2N, NT / G2M);
        gemm2_mma<<<grid, 256, G2_SMEM_FLOATS * 4>>>(out);
    }
}